// round 1
// baseline (speedup 1.0000x reference)
#include <cuda_runtime.h>
#include <math.h>

#define NB    4
#define CCH   64
#define NTOK  16384
#define NH    8
#define DH    64
#define INNER 512
#define EPSV  1e-12f

#define OUT_ELEMS  (NB * CCH * NTOK)   // 4194304
#define ATTN_ELEMS (NB * NH * DH * DH) // 131072

// Scratch (static device globals; no allocation allowed)
__device__ float g_Gpart[512 * CCH * CCH]; // per-block partial Gram matrices
__device__ float g_G[NB * CCH * CCH];      // reduced Gram per batch
__device__ float g_M[NB * CCH * CCH];      // effective 64x64 output matrix per batch

// ---------------------------------------------------------------------------
// K1: partial Gram. grid = 512 (4 batches x 128 chunks of 128 tokens).
// Each block computes a full 64x64 partial G over its 128 tokens.
// ---------------------------------------------------------------------------
__global__ __launch_bounds__(256) void gram_kernel(const float* __restrict__ x) {
    __shared__ float xs[64][33]; // [c][n-tile], pad to 33 to break bank conflicts
    const int b     = blockIdx.x >> 7;
    const int chunk = blockIdx.x & 127;
    const int n0    = chunk * 128;
    const int tid   = threadIdx.x;
    const int ty    = tid >> 4;
    const int tx    = tid & 15;

    const float* xb = x + (size_t)b * CCH * NTOK;

    float acc[4][4];
#pragma unroll
    for (int i = 0; i < 4; ++i)
#pragma unroll
        for (int j = 0; j < 4; ++j) acc[i][j] = 0.f;

    for (int t = 0; t < 4; ++t) {
        const int nb = n0 + t * 32;
#pragma unroll
        for (int r = 0; r < 8; ++r) {
            const int c = r * 8 + (tid >> 5);
            const int j = tid & 31;
            xs[c][j] = xb[c * NTOK + nb + j];
        }
        __syncthreads();
#pragma unroll 8
        for (int kk = 0; kk < 32; ++kk) {
            float a[4], bb[4];
#pragma unroll
            for (int i = 0; i < 4; ++i) a[i]  = xs[4 * ty + i][kk];
#pragma unroll
            for (int j = 0; j < 4; ++j) bb[j] = xs[4 * tx + j][kk];
#pragma unroll
            for (int i = 0; i < 4; ++i)
#pragma unroll
                for (int j = 0; j < 4; ++j) acc[i][j] = fmaf(a[i], bb[j], acc[i][j]);
        }
        __syncthreads();
    }

    float* gp = g_Gpart + (size_t)blockIdx.x * 4096;
#pragma unroll
    for (int i = 0; i < 4; ++i)
#pragma unroll
        for (int j = 0; j < 4; ++j)
            gp[(4 * ty + i) * 64 + (4 * tx + j)] = acc[i][j];
}

// ---------------------------------------------------------------------------
// K1b: reduce 128 partials per batch into g_G; also zero g_M.
// grid = 64 x 256 threads -> 16384 elements.
// ---------------------------------------------------------------------------
__global__ __launch_bounds__(256) void reduce_gram_kernel() {
    const int i = blockIdx.x * 256 + threadIdx.x; // 0..16383
    const int b = i >> 12;
    const int idx = i & 4095;
    float s = 0.f;
    const float* gp = g_Gpart + (size_t)(b * 128) * 4096 + idx;
#pragma unroll 4
    for (int p = 0; p < 128; ++p) s += gp[(size_t)p * 4096];
    g_G[i] = s;
    g_M[i] = 0.f;
}

// ---------------------------------------------------------------------------
// K2: per (batch, head, d-half) attention math.
// grid = 64 blocks (4b x 8h x 2 halves), 256 threads, dynamic smem.
// Computes attn (written to output) and accumulates M via atomics.
// ---------------------------------------------------------------------------
#define K2_SFLOATS 19072
#define K2_SBYTES  (K2_SFLOATS * 4)

__global__ __launch_bounds__(256) void attn_small_kernel(
    const float* __restrict__ Wq, const float* __restrict__ Wk,
    const float* __restrict__ Wv, const float* __restrict__ Wp,
    const float* __restrict__ rescale, float* __restrict__ attn_out) {
    extern __shared__ float smem[];
    float* sG  = smem;          // 64x65 : Gram
    float* sA  = smem + 4160;   // 64x65 : Wq_h, later Wv_h
    float* sB  = smem + 8320;   // 64x65 : Wk_h, later Wp_h (32 rows)
    float* sT  = smem + 12480;  // 64x65 : T1 = G@Wq_h, later P
    float* sS  = smem + 16640;  // 32x65 : T2t, later attn logits/probs
    float* red = smem + 18720;  // 256 scratch
    float* snq = smem + 18976;  // 64
    float* snk = smem + 19040;  // 32

    const int bx   = blockIdx.x;
    const int b    = bx >> 4;
    const int h    = (bx >> 1) & 7;
    const int half = bx & 1;
    const int d0   = half * 32;
    const int tid  = threadIdx.x;
    const int ty   = tid >> 4;
    const int tx   = tid & 15;

    // -- load G, Wq_h, Wk_h --
    for (int r = 0; r < 16; ++r) {
        const int idx = r * 256 + tid;     // 0..4095
        const int c = idx >> 6, c2 = idx & 63;
        sG[c * 65 + c2] = g_G[b * 4096 + idx];
        sA[c * 65 + c2] = Wq[c * INNER + h * 64 + c2];
        sB[c * 65 + c2] = Wk[c * INNER + h * 64 + c2];
    }
    __syncthreads();

    // -- T1 = G @ Wq_h  (64x64) --
    {
        float acc[4][4];
#pragma unroll
        for (int i = 0; i < 4; ++i)
#pragma unroll
            for (int j = 0; j < 4; ++j) acc[i][j] = 0.f;
#pragma unroll 4
        for (int cp = 0; cp < 64; ++cp) {
            float a[4], bb[4];
#pragma unroll
            for (int i = 0; i < 4; ++i) a[i]  = sG[(4 * ty + i) * 65 + cp];
#pragma unroll
            for (int j = 0; j < 4; ++j) bb[j] = sA[cp * 65 + 4 * tx + j];
#pragma unroll
            for (int i = 0; i < 4; ++i)
#pragma unroll
                for (int j = 0; j < 4; ++j) acc[i][j] = fmaf(a[i], bb[j], acc[i][j]);
        }
#pragma unroll
        for (int i = 0; i < 4; ++i)
#pragma unroll
            for (int j = 0; j < 4; ++j)
                sT[(4 * ty + i) * 65 + 4 * tx + j] = acc[i][j];
    }
    __syncthreads();

    // -- nq[e] = sqrt(sum_c Wq[c,e] * T1[c,e]) --
    {
        const int e = tid & 63, p = tid >> 6;
        float s = 0.f;
        for (int c = p * 16; c < p * 16 + 16; ++c) s += sA[c * 65 + e] * sT[c * 65 + e];
        red[p * 64 + e] = s;
    }
    __syncthreads();
    if (tid < 64) snq[tid] = sqrtf(red[tid] + red[64 + tid] + red[128 + tid] + red[192 + tid]);
    __syncthreads();

    // -- T2t[d, c] = sum_c' Wk[c', d0+d] * G[c', c]  (32x64, into sS) --
    {
        float acc[2][4] = {{0.f, 0.f, 0.f, 0.f}, {0.f, 0.f, 0.f, 0.f}};
#pragma unroll 4
        for (int cp = 0; cp < 64; ++cp) {
            float a[2], bb[4];
#pragma unroll
            for (int i = 0; i < 2; ++i) a[i]  = sB[cp * 65 + d0 + 2 * ty + i];
#pragma unroll
            for (int j = 0; j < 4; ++j) bb[j] = sG[cp * 65 + 4 * tx + j];
#pragma unroll
            for (int i = 0; i < 2; ++i)
#pragma unroll
                for (int j = 0; j < 4; ++j) acc[i][j] = fmaf(a[i], bb[j], acc[i][j]);
        }
#pragma unroll
        for (int i = 0; i < 2; ++i)
#pragma unroll
            for (int j = 0; j < 4; ++j)
                sS[(2 * ty + i) * 65 + 4 * tx + j] = acc[i][j];
    }
    __syncthreads();

    // -- nk[d] = sqrt(sum_c Wk[c, d0+d] * T2t[d, c]) --
    {
        const int d = tid & 31, p = tid >> 5;
        float s = 0.f;
        for (int c = p * 8; c < p * 8 + 8; ++c) s += sB[c * 65 + d0 + d] * sS[d * 65 + c];
        red[p * 32 + d] = s;
    }
    __syncthreads();
    if (tid < 32) {
        float s = 0.f;
#pragma unroll
        for (int p = 0; p < 8; ++p) s += red[p * 32 + tid];
        snk[tid] = sqrtf(s);
    }
    __syncthreads();

    // -- logits[d, e] = (Wk_d^T G Wq_e) / (nk nq) * rescale  (overwrite sS) --
    {
        float acc[2][4] = {{0.f, 0.f, 0.f, 0.f}, {0.f, 0.f, 0.f, 0.f}};
#pragma unroll 4
        for (int cp = 0; cp < 64; ++cp) {
            float a[2], bb[4];
#pragma unroll
            for (int i = 0; i < 2; ++i) a[i]  = sB[cp * 65 + d0 + 2 * ty + i];
#pragma unroll
            for (int j = 0; j < 4; ++j) bb[j] = sT[cp * 65 + 4 * tx + j];
#pragma unroll
            for (int i = 0; i < 2; ++i)
#pragma unroll
                for (int j = 0; j < 4; ++j) acc[i][j] = fmaf(a[i], bb[j], acc[i][j]);
        }
        const float rs = rescale[h];
#pragma unroll
        for (int i = 0; i < 2; ++i)
#pragma unroll
            for (int j = 0; j < 4; ++j) {
                const int d = 2 * ty + i, e = 4 * tx + j;
                sS[d * 65 + e] = acc[i][j] * rs /
                                 (fmaxf(snk[d], EPSV) * fmaxf(snq[e], EPSV));
            }
    }
    __syncthreads();

    // -- softmax over e per row d; write attn to output --
    {
        const int w = tid >> 5, lane = tid & 31;
        for (int r = 0; r < 4; ++r) {
            const int d = w * 4 + r;
            float v0 = sS[d * 65 + lane];
            float v1 = sS[d * 65 + 32 + lane];
            float m = fmaxf(v0, v1);
#pragma unroll
            for (int o = 16; o > 0; o >>= 1) m = fmaxf(m, __shfl_xor_sync(0xffffffffu, m, o));
            float e0 = __expf(v0 - m), e1 = __expf(v1 - m);
            float s = e0 + e1;
#pragma unroll
            for (int o = 16; o > 0; o >>= 1) s += __shfl_xor_sync(0xffffffffu, s, o);
            const float inv = 1.f / s;
            e0 *= inv; e1 *= inv;
            sS[d * 65 + lane]      = e0;
            sS[d * 65 + 32 + lane] = e1;
            float* ao = attn_out + (((size_t)(b * NH + h) * DH) + d0 + d) * DH;
            ao[lane]      = e0;
            ao[32 + lane] = e1;
        }
    }
    __syncthreads();

    // -- reload: sA <- Wv_h (64x64), sB <- Wp_h rows [d0, d0+32) --
    for (int r = 0; r < 16; ++r) {
        const int idx = r * 256 + tid;
        const int c = idx >> 6, e = idx & 63;
        sA[c * 65 + e] = Wv[c * INNER + h * 64 + e];
    }
    for (int r = 0; r < 8; ++r) {
        const int idx = r * 256 + tid;  // 0..2047
        const int d = idx >> 6, c = idx & 63;
        sB[d * 65 + c] = Wp[(h * 64 + d0 + d) * CCH + c];
    }
    __syncthreads();

    // -- P[e, c] = sum_d attn[d, e] * Wp[d0+d, c]  (into sT) --
    {
        float acc[4][4];
#pragma unroll
        for (int i = 0; i < 4; ++i)
#pragma unroll
            for (int j = 0; j < 4; ++j) acc[i][j] = 0.f;
#pragma unroll 4
        for (int dk = 0; dk < 32; ++dk) {
            float a[4], bb[4];
#pragma unroll
            for (int i = 0; i < 4; ++i) a[i]  = sS[dk * 65 + 4 * ty + i];
#pragma unroll
            for (int j = 0; j < 4; ++j) bb[j] = sB[dk * 65 + 4 * tx + j];
#pragma unroll
            for (int i = 0; i < 4; ++i)
#pragma unroll
                for (int j = 0; j < 4; ++j) acc[i][j] = fmaf(a[i], bb[j], acc[i][j]);
        }
#pragma unroll
        for (int i = 0; i < 4; ++i)
#pragma unroll
            for (int j = 0; j < 4; ++j)
                sT[(4 * ty + i) * 65 + 4 * tx + j] = acc[i][j];
    }
    __syncthreads();

    // -- M[c1, c2] += sum_e Wv[c1, e] * P[e, c2] --
    {
        float acc[4][4];
#pragma unroll
        for (int i = 0; i < 4; ++i)
#pragma unroll
            for (int j = 0; j < 4; ++j) acc[i][j] = 0.f;
#pragma unroll 4
        for (int e = 0; e < 64; ++e) {
            float a[4], bb[4];
#pragma unroll
            for (int i = 0; i < 4; ++i) a[i]  = sA[(4 * ty + i) * 65 + e];
#pragma unroll
            for (int j = 0; j < 4; ++j) bb[j] = sT[e * 65 + 4 * tx + j];
#pragma unroll
            for (int i = 0; i < 4; ++i)
#pragma unroll
                for (int j = 0; j < 4; ++j) acc[i][j] = fmaf(a[i], bb[j], acc[i][j]);
        }
#pragma unroll
        for (int i = 0; i < 4; ++i)
#pragma unroll
            for (int j = 0; j < 4; ++j)
                atomicAdd(&g_M[b * 4096 + (4 * ty + i) * 64 + (4 * tx + j)], acc[i][j]);
    }
}

// ---------------------------------------------------------------------------
// K3: out[b, c, n] = sum_c' x[b, c', n] * M_b[c', c] + bp[c]
// grid = 256 (4 batches x 64 segments of 256 tokens), 256 threads.
// ---------------------------------------------------------------------------
__global__ __launch_bounds__(256) void out_kernel(const float* __restrict__ x,
                                                  const float* __restrict__ bp,
                                                  float* __restrict__ out) {
    __shared__ float Ms[64][64];  // [c'][c]
    __shared__ float xs[64][65];  // [c'][n-tile]
    const int b   = blockIdx.x >> 6;
    const int seg = blockIdx.x & 63;
    const int n0  = seg * 256;
    const int tid = threadIdx.x;
    const int ty  = tid >> 4;
    const int tx  = tid & 15;

    for (int r = 0; r < 16; ++r) {
        const int idx = r * 256 + tid;
        Ms[idx >> 6][idx & 63] = g_M[b * 4096 + idx];
    }
    float bpv[4];
#pragma unroll
    for (int i = 0; i < 4; ++i) bpv[i] = bp[4 * ty + i];

    const float* xb = x + (size_t)b * CCH * NTOK;
    float* ob = out + (size_t)b * CCH * NTOK;
    __syncthreads();

    for (int t = 0; t < 4; ++t) {
        const int nb = n0 + t * 64;
        for (int r = 0; r < 16; ++r) {
            const int c = r * 4 + (tid >> 6);
            const int j = tid & 63;
            xs[c][j] = xb[c * NTOK + nb + j];
        }
        __syncthreads();

        float acc[4][4];
#pragma unroll
        for (int i = 0; i < 4; ++i)
#pragma unroll
            for (int j = 0; j < 4; ++j) acc[i][j] = 0.f;
#pragma unroll 8
        for (int cp = 0; cp < 64; ++cp) {
            float a[4], bb[4];
#pragma unroll
            for (int i = 0; i < 4; ++i) a[i]  = Ms[cp][4 * ty + i];
#pragma unroll
            for (int j = 0; j < 4; ++j) bb[j] = xs[cp][4 * tx + j];
#pragma unroll
            for (int i = 0; i < 4; ++i)
#pragma unroll
                for (int j = 0; j < 4; ++j) acc[i][j] = fmaf(a[i], bb[j], acc[i][j]);
        }
        __syncthreads();

#pragma unroll
        for (int i = 0; i < 4; ++i) {
            float4 v;
            v.x = acc[i][0] + bpv[i];
            v.y = acc[i][1] + bpv[i];
            v.z = acc[i][2] + bpv[i];
            v.w = acc[i][3] + bpv[i];
            *reinterpret_cast<float4*>(&ob[(4 * ty + i) * NTOK + nb + 4 * tx]) = v;
        }
    }
}

// ---------------------------------------------------------------------------
extern "C" void kernel_launch(void* const* d_in, const int* in_sizes, int n_in,
                              void* d_out, int out_size) {
    const float* x       = (const float*)d_in[0];
    const float* Wq      = (const float*)d_in[1];
    const float* Wk      = (const float*)d_in[2];
    const float* Wv      = (const float*)d_in[3];
    const float* Wp      = (const float*)d_in[4];
    const float* bp      = (const float*)d_in[5];
    const float* rescale = (const float*)d_in[6];
    float* out      = (float*)d_out;
    float* attn_out = out + OUT_ELEMS;

    cudaFuncSetAttribute(attn_small_kernel,
                         cudaFuncAttributeMaxDynamicSharedMemorySize, K2_SBYTES);

    gram_kernel<<<512, 256>>>(x);
    reduce_gram_kernel<<<64, 256>>>();
    attn_small_kernel<<<64, 256, K2_SBYTES>>>(Wq, Wk, Wv, Wp, rescale, attn_out);
    out_kernel<<<256, 256>>>(x, bp, out);
}

// round 2
// speedup vs baseline: 1.1525x; 1.1525x over previous
#include <cuda_runtime.h>
#include <math.h>

#define NB    4
#define CCH   64
#define NTOK  16384
#define NH    8
#define DH    64
#define INNER 512
#define EPSV  1e-12f

#define OUT_ELEMS  (NB * CCH * NTOK)   // 4194304
#define ATTN_ELEMS (NB * NH * DH * DH) // 131072

// Scratch (static device globals; no allocation allowed)
__device__ float g_Gpart[512 * CCH * CCH]; // per-block partial Gram matrices
__device__ float g_G[NB * CCH * CCH];      // reduced Gram per batch
__device__ float g_M[NB * CCH * CCH];      // effective 64x64 output matrix per batch

// ---------------------------------------------------------------------------
// K1: partial Gram. grid = 512 (4 batches x 128 chunks of 128 tokens).
// Token-major smem layout so BOTH 4x4-tile operands are contiguous float4.
// Only upper-triangle tiles computed (G symmetric), mirrored on store.
// ---------------------------------------------------------------------------
__global__ __launch_bounds__(256) void gram_kernel(const float* __restrict__ x) {
    __shared__ float xs[128][68]; // [token][c]; stride 68 => 16B-aligned rows
    const int b     = blockIdx.x >> 7;
    const int chunk = blockIdx.x & 127;
    const int n0    = chunk * 128;
    const int tid   = threadIdx.x;

    // Map threads 0..135 to upper-triangle 4x4 tiles (ii <= jj), rest idle.
    int ii = 0, jj = 0;
    const bool active = tid < 136;
    if (active) {
        int rem = tid, i = 0;
        while (rem >= 16 - i) { rem -= 16 - i; ++i; }
        ii = i; jj = i + rem;
    }

    const float* xb = x + (size_t)b * CCH * NTOK;

    // Fill smem (transposed): 2048 float4 global reads, 8 per thread.
#pragma unroll
    for (int r = 0; r < 8; ++r) {
        const int q  = r * 256 + tid;
        const int c  = q >> 5;        // 0..63
        const int nq = q & 31;        // float4 index along tokens
        const float4 v = *reinterpret_cast<const float4*>(&xb[c * NTOK + n0 + 4 * nq]);
        xs[4 * nq + 0][c] = v.x;
        xs[4 * nq + 1][c] = v.y;
        xs[4 * nq + 2][c] = v.z;
        xs[4 * nq + 3][c] = v.w;
    }
    __syncthreads();

    float acc[4][4];
#pragma unroll
    for (int i = 0; i < 4; ++i)
#pragma unroll
        for (int j = 0; j < 4; ++j) acc[i][j] = 0.f;

    if (active) {
#pragma unroll 4
        for (int kk = 0; kk < 128; ++kk) {
            const float4 a4 = *reinterpret_cast<const float4*>(&xs[kk][4 * ii]);
            const float4 b4 = *reinterpret_cast<const float4*>(&xs[kk][4 * jj]);
            const float a[4] = {a4.x, a4.y, a4.z, a4.w};
            const float bb[4] = {b4.x, b4.y, b4.z, b4.w};
#pragma unroll
            for (int i = 0; i < 4; ++i)
#pragma unroll
                for (int j = 0; j < 4; ++j) acc[i][j] = fmaf(a[i], bb[j], acc[i][j]);
        }

        float* gp = g_Gpart + (size_t)blockIdx.x * 4096;
#pragma unroll
        for (int i = 0; i < 4; ++i)
#pragma unroll
            for (int j = 0; j < 4; ++j)
                gp[(4 * ii + i) * 64 + (4 * jj + j)] = acc[i][j];
        if (ii != jj) {
#pragma unroll
            for (int i = 0; i < 4; ++i)
#pragma unroll
                for (int j = 0; j < 4; ++j)
                    gp[(4 * jj + j) * 64 + (4 * ii + i)] = acc[i][j];
        }
    }
}

// ---------------------------------------------------------------------------
// K1b: reduce 128 partials per batch into g_G; also zero g_M.
// ---------------------------------------------------------------------------
__global__ __launch_bounds__(256) void reduce_gram_kernel() {
    const int i = blockIdx.x * 256 + threadIdx.x; // 0..16383
    const int b = i >> 12;
    const int idx = i & 4095;
    float s = 0.f;
    const float* gp = g_Gpart + (size_t)(b * 128) * 4096 + idx;
#pragma unroll 8
    for (int p = 0; p < 128; ++p) s += gp[(size_t)p * 4096];
    g_G[i] = s;
    g_M[i] = 0.f;
}

// ---------------------------------------------------------------------------
// K2: per (batch, head, d-half) attention math. (unchanged from R1)
// ---------------------------------------------------------------------------
#define K2_SFLOATS 19072
#define K2_SBYTES  (K2_SFLOATS * 4)

__global__ __launch_bounds__(256) void attn_small_kernel(
    const float* __restrict__ Wq, const float* __restrict__ Wk,
    const float* __restrict__ Wv, const float* __restrict__ Wp,
    const float* __restrict__ rescale, float* __restrict__ attn_out) {
    extern __shared__ float smem[];
    float* sG  = smem;          // 64x65 : Gram
    float* sA  = smem + 4160;   // 64x65 : Wq_h, later Wv_h
    float* sB  = smem + 8320;   // 64x65 : Wk_h, later Wp_h (32 rows)
    float* sT  = smem + 12480;  // 64x65 : T1 = G@Wq_h, later P
    float* sS  = smem + 16640;  // 32x65 : T2t, later attn logits/probs
    float* red = smem + 18720;  // 256 scratch
    float* snq = smem + 18976;  // 64
    float* snk = smem + 19040;  // 32

    const int bx   = blockIdx.x;
    const int b    = bx >> 4;
    const int h    = (bx >> 1) & 7;
    const int half = bx & 1;
    const int d0   = half * 32;
    const int tid  = threadIdx.x;
    const int ty   = tid >> 4;
    const int tx   = tid & 15;

    for (int r = 0; r < 16; ++r) {
        const int idx = r * 256 + tid;
        const int c = idx >> 6, c2 = idx & 63;
        sG[c * 65 + c2] = g_G[b * 4096 + idx];
        sA[c * 65 + c2] = Wq[c * INNER + h * 64 + c2];
        sB[c * 65 + c2] = Wk[c * INNER + h * 64 + c2];
    }
    __syncthreads();

    // T1 = G @ Wq_h
    {
        float acc[4][4];
#pragma unroll
        for (int i = 0; i < 4; ++i)
#pragma unroll
            for (int j = 0; j < 4; ++j) acc[i][j] = 0.f;
#pragma unroll 4
        for (int cp = 0; cp < 64; ++cp) {
            float a[4], bb[4];
#pragma unroll
            for (int i = 0; i < 4; ++i) a[i]  = sG[(4 * ty + i) * 65 + cp];
#pragma unroll
            for (int j = 0; j < 4; ++j) bb[j] = sA[cp * 65 + 4 * tx + j];
#pragma unroll
            for (int i = 0; i < 4; ++i)
#pragma unroll
                for (int j = 0; j < 4; ++j) acc[i][j] = fmaf(a[i], bb[j], acc[i][j]);
        }
#pragma unroll
        for (int i = 0; i < 4; ++i)
#pragma unroll
            for (int j = 0; j < 4; ++j)
                sT[(4 * ty + i) * 65 + 4 * tx + j] = acc[i][j];
    }
    __syncthreads();

    // nq
    {
        const int e = tid & 63, p = tid >> 6;
        float s = 0.f;
        for (int c = p * 16; c < p * 16 + 16; ++c) s += sA[c * 65 + e] * sT[c * 65 + e];
        red[p * 64 + e] = s;
    }
    __syncthreads();
    if (tid < 64) snq[tid] = sqrtf(red[tid] + red[64 + tid] + red[128 + tid] + red[192 + tid]);
    __syncthreads();

    // T2t = Wk_h^T G (32x64)
    {
        float acc[2][4] = {{0.f, 0.f, 0.f, 0.f}, {0.f, 0.f, 0.f, 0.f}};
#pragma unroll 4
        for (int cp = 0; cp < 64; ++cp) {
            float a[2], bb[4];
#pragma unroll
            for (int i = 0; i < 2; ++i) a[i]  = sB[cp * 65 + d0 + 2 * ty + i];
#pragma unroll
            for (int j = 0; j < 4; ++j) bb[j] = sG[cp * 65 + 4 * tx + j];
#pragma unroll
            for (int i = 0; i < 2; ++i)
#pragma unroll
                for (int j = 0; j < 4; ++j) acc[i][j] = fmaf(a[i], bb[j], acc[i][j]);
        }
#pragma unroll
        for (int i = 0; i < 2; ++i)
#pragma unroll
            for (int j = 0; j < 4; ++j)
                sS[(2 * ty + i) * 65 + 4 * tx + j] = acc[i][j];
    }
    __syncthreads();

    // nk
    {
        const int d = tid & 31, p = tid >> 5;
        float s = 0.f;
        for (int c = p * 8; c < p * 8 + 8; ++c) s += sB[c * 65 + d0 + d] * sS[d * 65 + c];
        red[p * 32 + d] = s;
    }
    __syncthreads();
    if (tid < 32) {
        float s = 0.f;
#pragma unroll
        for (int p = 0; p < 8; ++p) s += red[p * 32 + tid];
        snk[tid] = sqrtf(s);
    }
    __syncthreads();

    // logits
    {
        float acc[2][4] = {{0.f, 0.f, 0.f, 0.f}, {0.f, 0.f, 0.f, 0.f}};
#pragma unroll 4
        for (int cp = 0; cp < 64; ++cp) {
            float a[2], bb[4];
#pragma unroll
            for (int i = 0; i < 2; ++i) a[i]  = sB[cp * 65 + d0 + 2 * ty + i];
#pragma unroll
            for (int j = 0; j < 4; ++j) bb[j] = sT[cp * 65 + 4 * tx + j];
#pragma unroll
            for (int i = 0; i < 2; ++i)
#pragma unroll
                for (int j = 0; j < 4; ++j) acc[i][j] = fmaf(a[i], bb[j], acc[i][j]);
        }
        const float rs = rescale[h];
#pragma unroll
        for (int i = 0; i < 2; ++i)
#pragma unroll
            for (int j = 0; j < 4; ++j) {
                const int d = 2 * ty + i, e = 4 * tx + j;
                sS[d * 65 + e] = acc[i][j] * rs /
                                 (fmaxf(snk[d], EPSV) * fmaxf(snq[e], EPSV));
            }
    }
    __syncthreads();

    // softmax + write attn
    {
        const int w = tid >> 5, lane = tid & 31;
        for (int r = 0; r < 4; ++r) {
            const int d = w * 4 + r;
            float v0 = sS[d * 65 + lane];
            float v1 = sS[d * 65 + 32 + lane];
            float m = fmaxf(v0, v1);
#pragma unroll
            for (int o = 16; o > 0; o >>= 1) m = fmaxf(m, __shfl_xor_sync(0xffffffffu, m, o));
            float e0 = __expf(v0 - m), e1 = __expf(v1 - m);
            float s = e0 + e1;
#pragma unroll
            for (int o = 16; o > 0; o >>= 1) s += __shfl_xor_sync(0xffffffffu, s, o);
            const float inv = 1.f / s;
            e0 *= inv; e1 *= inv;
            sS[d * 65 + lane]      = e0;
            sS[d * 65 + 32 + lane] = e1;
            float* ao = attn_out + (((size_t)(b * NH + h) * DH) + d0 + d) * DH;
            ao[lane]      = e0;
            ao[32 + lane] = e1;
        }
    }
    __syncthreads();

    // reload Wv_h, Wp_h
    for (int r = 0; r < 16; ++r) {
        const int idx = r * 256 + tid;
        const int c = idx >> 6, e = idx & 63;
        sA[c * 65 + e] = Wv[c * INNER + h * 64 + e];
    }
    for (int r = 0; r < 8; ++r) {
        const int idx = r * 256 + tid;
        const int d = idx >> 6, c = idx & 63;
        sB[d * 65 + c] = Wp[(h * 64 + d0 + d) * CCH + c];
    }
    __syncthreads();

    // P = attn^T Wp_h
    {
        float acc[4][4];
#pragma unroll
        for (int i = 0; i < 4; ++i)
#pragma unroll
            for (int j = 0; j < 4; ++j) acc[i][j] = 0.f;
#pragma unroll 4
        for (int dk = 0; dk < 32; ++dk) {
            float a[4], bb[4];
#pragma unroll
            for (int i = 0; i < 4; ++i) a[i]  = sS[dk * 65 + 4 * ty + i];
#pragma unroll
            for (int j = 0; j < 4; ++j) bb[j] = sB[dk * 65 + 4 * tx + j];
#pragma unroll
            for (int i = 0; i < 4; ++i)
#pragma unroll
                for (int j = 0; j < 4; ++j) acc[i][j] = fmaf(a[i], bb[j], acc[i][j]);
        }
#pragma unroll
        for (int i = 0; i < 4; ++i)
#pragma unroll
            for (int j = 0; j < 4; ++j)
                sT[(4 * ty + i) * 65 + 4 * tx + j] = acc[i][j];
    }
    __syncthreads();

    // M += Wv_h @ P
    {
        float acc[4][4];
#pragma unroll
        for (int i = 0; i < 4; ++i)
#pragma unroll
            for (int j = 0; j < 4; ++j) acc[i][j] = 0.f;
#pragma unroll 4
        for (int e = 0; e < 64; ++e) {
            float a[4], bb[4];
#pragma unroll
            for (int i = 0; i < 4; ++i) a[i]  = sA[(4 * ty + i) * 65 + e];
#pragma unroll
            for (int j = 0; j < 4; ++j) bb[j] = sT[e * 65 + 4 * tx + j];
#pragma unroll
            for (int i = 0; i < 4; ++i)
#pragma unroll
                for (int j = 0; j < 4; ++j) acc[i][j] = fmaf(a[i], bb[j], acc[i][j]);
        }
#pragma unroll
        for (int i = 0; i < 4; ++i)
#pragma unroll
            for (int j = 0; j < 4; ++j)
                atomicAdd(&g_M[b * 4096 + (4 * ty + i) * 64 + (4 * tx + j)], acc[i][j]);
    }
}

// ---------------------------------------------------------------------------
// K3: out[b, c, n] = sum_c' x[b, c', n] * M_b[c', c] + bp[c]
// Vectorized LDS.128 operands: 2 LDS + 16 FFMA per k-step per thread.
// ---------------------------------------------------------------------------
__global__ __launch_bounds__(256) void out_kernel(const float* __restrict__ x,
                                                  const float* __restrict__ bp,
                                                  float* __restrict__ out) {
    __shared__ float Ms[64][64];  // [c'][c] (256B rows, 16B aligned)
    __shared__ float xs[64][68];  // [c'][n-tile], stride 68 => 16B-aligned rows
    const int b   = blockIdx.x >> 6;
    const int seg = blockIdx.x & 63;
    const int n0  = seg * 256;
    const int tid = threadIdx.x;
    const int ty  = tid >> 4;
    const int tx  = tid & 15;

    // load M via float4 (1024 f4 / 256 thr = 4 each)
#pragma unroll
    for (int r = 0; r < 4; ++r) {
        const int q    = r * 256 + tid;
        const int row  = q >> 4;
        const int col4 = q & 15;
        *reinterpret_cast<float4*>(&Ms[row][4 * col4]) =
            *reinterpret_cast<const float4*>(&g_M[b * 4096 + row * 64 + 4 * col4]);
    }
    float bpv[4];
#pragma unroll
    for (int i = 0; i < 4; ++i) bpv[i] = bp[4 * ty + i];

    const float* xb = x + (size_t)b * CCH * NTOK;
    float* ob = out + (size_t)b * CCH * NTOK;
    __syncthreads();

    for (int t = 0; t < 4; ++t) {
        const int nb = n0 + t * 64;
        // fill xs via float4 (1024 f4 / 256 thr = 4 each)
#pragma unroll
        for (int r = 0; r < 4; ++r) {
            const int q    = r * 256 + tid;
            const int c    = q >> 4;
            const int col4 = q & 15;
            *reinterpret_cast<float4*>(&xs[c][4 * col4]) =
                *reinterpret_cast<const float4*>(&xb[c * NTOK + nb + 4 * col4]);
        }
        __syncthreads();

        float acc[4][4];
#pragma unroll
        for (int i = 0; i < 4; ++i)
#pragma unroll
            for (int j = 0; j < 4; ++j) acc[i][j] = 0.f;
#pragma unroll 4
        for (int cp = 0; cp < 64; ++cp) {
            const float4 a4 = *reinterpret_cast<const float4*>(&Ms[cp][4 * ty]);
            const float4 b4 = *reinterpret_cast<const float4*>(&xs[cp][4 * tx]);
            const float a[4] = {a4.x, a4.y, a4.z, a4.w};
            const float bb[4] = {b4.x, b4.y, b4.z, b4.w};
#pragma unroll
            for (int i = 0; i < 4; ++i)
#pragma unroll
                for (int j = 0; j < 4; ++j) acc[i][j] = fmaf(a[i], bb[j], acc[i][j]);
        }
        __syncthreads();

#pragma unroll
        for (int i = 0; i < 4; ++i) {
            float4 v;
            v.x = acc[i][0] + bpv[i];
            v.y = acc[i][1] + bpv[i];
            v.z = acc[i][2] + bpv[i];
            v.w = acc[i][3] + bpv[i];
            *reinterpret_cast<float4*>(&ob[(4 * ty + i) * NTOK + nb + 4 * tx]) = v;
        }
    }
}

// ---------------------------------------------------------------------------
extern "C" void kernel_launch(void* const* d_in, const int* in_sizes, int n_in,
                              void* d_out, int out_size) {
    const float* x       = (const float*)d_in[0];
    const float* Wq      = (const float*)d_in[1];
    const float* Wk      = (const float*)d_in[2];
    const float* Wv      = (const float*)d_in[3];
    const float* Wp      = (const float*)d_in[4];
    const float* bp      = (const float*)d_in[5];
    const float* rescale = (const float*)d_in[6];
    float* out      = (float*)d_out;
    float* attn_out = out + OUT_ELEMS;

    cudaFuncSetAttribute(attn_small_kernel,
                         cudaFuncAttributeMaxDynamicSharedMemorySize, K2_SBYTES);

    gram_kernel<<<512, 256>>>(x);
    reduce_gram_kernel<<<64, 256>>>();
    attn_small_kernel<<<64, 256, K2_SBYTES>>>(Wq, Wk, Wv, Wp, rescale, attn_out);
    out_kernel<<<256, 256>>>(x, bp, out);
}

// round 3
// speedup vs baseline: 1.2693x; 1.1013x over previous
#include <cuda_runtime.h>
#include <math.h>

#define NB    4
#define CCH   64
#define NTOK  16384
#define NH    8
#define DH    64
#define INNER 512
#define EPSV  1e-12f

#define OUT_ELEMS  (NB * CCH * NTOK)   // 4194304
#define ATTN_ELEMS (NB * NH * DH * DH) // 131072

typedef unsigned long long ull;

// Scratch (static device globals; no allocation allowed)
__device__ float g_Gpart[512 * CCH * CCH]; // per-block partial Gram matrices
__device__ float g_G[NB * CCH * CCH];      // reduced Gram per batch
__device__ float g_M[NB * CCH * CCH];      // effective 64x64 output matrix per batch

// ---- packed f32x2 helpers (sm_103a FFMA2) ----
__device__ __forceinline__ ull fma2(ull a, ull b, ull c) {
    ull d;
    asm("fma.rn.f32x2 %0, %1, %2, %3;" : "=l"(d) : "l"(a), "l"(b), "l"(c));
    return d;
}
__device__ __forceinline__ ull pk2(float v) {
    ull d;
    asm("mov.b64 %0, {%1, %1};" : "=l"(d) : "f"(v));
    return d;
}
union U2 { ull u; float2 f; };
__device__ __forceinline__ float2 up2(ull v) { U2 t; t.u = v; return t.f; }

// ---------------------------------------------------------------------------
// K1: partial Gram. grid = 512 (4 batches x 128 chunks of 128 tokens).
// Token-major smem; all 256 threads compute 4x4 tiles of full 64x64 via
// packed FFMA2 (8 per k-step). Two 64-token sub-tiles per block.
// ---------------------------------------------------------------------------
__global__ __launch_bounds__(256) void gram_kernel(const float* __restrict__ x) {
    __shared__ float xs[64][68]; // [token][c]; stride 68 -> 16B-aligned rows
    const int b     = blockIdx.x >> 7;
    const int chunk = blockIdx.x & 127;
    const int n0    = chunk * 128;
    const int tid   = threadIdx.x;
    const int ty    = tid >> 4;
    const int tx    = tid & 15;
    const int lane  = tid & 31;
    const int warp  = tid >> 5;

    const float* xb = x + (size_t)b * CCH * NTOK;

    ull accA[4], accB[4];
#pragma unroll
    for (int i = 0; i < 4; ++i) { accA[i] = 0ull; accB[i] = 0ull; }

    for (int t = 0; t < 2; ++t) {
        const int nt = n0 + t * 64;
        // transposed fill with lane remap: c varies within warp (low write conflicts)
#pragma unroll
        for (int r = 0; r < 4; ++r) {
            const int W  = r * 8 + warp;                 // 0..31
            const int c  = ((W & 15) << 2) + (lane >> 3);
            const int nq = ((W >> 4) << 3) + (lane & 7); // 0..15
            const float4 v = *reinterpret_cast<const float4*>(&xb[c * NTOK + nt + 4 * nq]);
            xs[4 * nq + 0][c] = v.x;
            xs[4 * nq + 1][c] = v.y;
            xs[4 * nq + 2][c] = v.z;
            xs[4 * nq + 3][c] = v.w;
        }
        __syncthreads();

#pragma unroll 4
        for (int kk = 0; kk < 64; ++kk) {
            const float4 a4 = *reinterpret_cast<const float4*>(&xs[kk][4 * ty]);
            const ulonglong2 bb = *reinterpret_cast<const ulonglong2*>(&xs[kk][4 * tx]);
            const ull aa0 = pk2(a4.x), aa1 = pk2(a4.y), aa2 = pk2(a4.z), aa3 = pk2(a4.w);
            accA[0] = fma2(aa0, bb.x, accA[0]); accB[0] = fma2(aa0, bb.y, accB[0]);
            accA[1] = fma2(aa1, bb.x, accA[1]); accB[1] = fma2(aa1, bb.y, accB[1]);
            accA[2] = fma2(aa2, bb.x, accA[2]); accB[2] = fma2(aa2, bb.y, accB[2]);
            accA[3] = fma2(aa3, bb.x, accA[3]); accB[3] = fma2(aa3, bb.y, accB[3]);
        }
        __syncthreads();
    }

    float* gp = g_Gpart + (size_t)blockIdx.x * 4096;
#pragma unroll
    for (int i = 0; i < 4; ++i) {
        const float2 lo = up2(accA[i]);
        const float2 hi = up2(accB[i]);
        float4 v; v.x = lo.x; v.y = lo.y; v.z = hi.x; v.w = hi.y;
        *reinterpret_cast<float4*>(&gp[(4 * ty + i) * 64 + 4 * tx]) = v;
    }
}

// ---------------------------------------------------------------------------
// K1b: reduce 128 partials per batch into g_G; also zero g_M.
// ---------------------------------------------------------------------------
__global__ __launch_bounds__(256) void reduce_gram_kernel() {
    const int i = blockIdx.x * 256 + threadIdx.x; // 0..16383
    const int b = i >> 12;
    const int idx = i & 4095;
    float s = 0.f;
    const float* gp = g_Gpart + (size_t)(b * 128) * 4096 + idx;
#pragma unroll 8
    for (int p = 0; p < 128; ++p) s += gp[(size_t)p * 4096];
    g_G[i] = s;
    g_M[i] = 0.f;
}

// ---------------------------------------------------------------------------
// K2: per (batch, head, d-half) attention math. (unchanged)
// ---------------------------------------------------------------------------
#define K2_SFLOATS 19072
#define K2_SBYTES  (K2_SFLOATS * 4)

__global__ __launch_bounds__(256) void attn_small_kernel(
    const float* __restrict__ Wq, const float* __restrict__ Wk,
    const float* __restrict__ Wv, const float* __restrict__ Wp,
    const float* __restrict__ rescale, float* __restrict__ attn_out) {
    extern __shared__ float smem[];
    float* sG  = smem;          // 64x65 : Gram
    float* sA  = smem + 4160;   // 64x65 : Wq_h, later Wv_h
    float* sB  = smem + 8320;   // 64x65 : Wk_h, later Wp_h (32 rows)
    float* sT  = smem + 12480;  // 64x65 : T1 = G@Wq_h, later P
    float* sS  = smem + 16640;  // 32x65 : T2t, later attn logits/probs
    float* red = smem + 18720;  // 256 scratch
    float* snq = smem + 18976;  // 64
    float* snk = smem + 19040;  // 32

    const int bx   = blockIdx.x;
    const int b    = bx >> 4;
    const int h    = (bx >> 1) & 7;
    const int half = bx & 1;
    const int d0   = half * 32;
    const int tid  = threadIdx.x;
    const int ty   = tid >> 4;
    const int tx   = tid & 15;

    for (int r = 0; r < 16; ++r) {
        const int idx = r * 256 + tid;
        const int c = idx >> 6, c2 = idx & 63;
        sG[c * 65 + c2] = g_G[b * 4096 + idx];
        sA[c * 65 + c2] = Wq[c * INNER + h * 64 + c2];
        sB[c * 65 + c2] = Wk[c * INNER + h * 64 + c2];
    }
    __syncthreads();

    // T1 = G @ Wq_h
    {
        float acc[4][4];
#pragma unroll
        for (int i = 0; i < 4; ++i)
#pragma unroll
            for (int j = 0; j < 4; ++j) acc[i][j] = 0.f;
#pragma unroll 4
        for (int cp = 0; cp < 64; ++cp) {
            float a[4], bb[4];
#pragma unroll
            for (int i = 0; i < 4; ++i) a[i]  = sG[(4 * ty + i) * 65 + cp];
#pragma unroll
            for (int j = 0; j < 4; ++j) bb[j] = sA[cp * 65 + 4 * tx + j];
#pragma unroll
            for (int i = 0; i < 4; ++i)
#pragma unroll
                for (int j = 0; j < 4; ++j) acc[i][j] = fmaf(a[i], bb[j], acc[i][j]);
        }
#pragma unroll
        for (int i = 0; i < 4; ++i)
#pragma unroll
            for (int j = 0; j < 4; ++j)
                sT[(4 * ty + i) * 65 + 4 * tx + j] = acc[i][j];
    }
    __syncthreads();

    // nq
    {
        const int e = tid & 63, p = tid >> 6;
        float s = 0.f;
        for (int c = p * 16; c < p * 16 + 16; ++c) s += sA[c * 65 + e] * sT[c * 65 + e];
        red[p * 64 + e] = s;
    }
    __syncthreads();
    if (tid < 64) snq[tid] = sqrtf(red[tid] + red[64 + tid] + red[128 + tid] + red[192 + tid]);
    __syncthreads();

    // T2t = Wk_h^T G (32x64)
    {
        float acc[2][4] = {{0.f, 0.f, 0.f, 0.f}, {0.f, 0.f, 0.f, 0.f}};
#pragma unroll 4
        for (int cp = 0; cp < 64; ++cp) {
            float a[2], bb[4];
#pragma unroll
            for (int i = 0; i < 2; ++i) a[i]  = sB[cp * 65 + d0 + 2 * ty + i];
#pragma unroll
            for (int j = 0; j < 4; ++j) bb[j] = sG[cp * 65 + 4 * tx + j];
#pragma unroll
            for (int i = 0; i < 2; ++i)
#pragma unroll
                for (int j = 0; j < 4; ++j) acc[i][j] = fmaf(a[i], bb[j], acc[i][j]);
        }
#pragma unroll
        for (int i = 0; i < 2; ++i)
#pragma unroll
            for (int j = 0; j < 4; ++j)
                sS[(2 * ty + i) * 65 + 4 * tx + j] = acc[i][j];
    }
    __syncthreads();

    // nk
    {
        const int d = tid & 31, p = tid >> 5;
        float s = 0.f;
        for (int c = p * 8; c < p * 8 + 8; ++c) s += sB[c * 65 + d0 + d] * sS[d * 65 + c];
        red[p * 32 + d] = s;
    }
    __syncthreads();
    if (tid < 32) {
        float s = 0.f;
#pragma unroll
        for (int p = 0; p < 8; ++p) s += red[p * 32 + tid];
        snk[tid] = sqrtf(s);
    }
    __syncthreads();

    // logits
    {
        float acc[2][4] = {{0.f, 0.f, 0.f, 0.f}, {0.f, 0.f, 0.f, 0.f}};
#pragma unroll 4
        for (int cp = 0; cp < 64; ++cp) {
            float a[2], bb[4];
#pragma unroll
            for (int i = 0; i < 2; ++i) a[i]  = sB[cp * 65 + d0 + 2 * ty + i];
#pragma unroll
            for (int j = 0; j < 4; ++j) bb[j] = sT[cp * 65 + 4 * tx + j];
#pragma unroll
            for (int i = 0; i < 2; ++i)
#pragma unroll
                for (int j = 0; j < 4; ++j) acc[i][j] = fmaf(a[i], bb[j], acc[i][j]);
        }
        const float rs = rescale[h];
#pragma unroll
        for (int i = 0; i < 2; ++i)
#pragma unroll
            for (int j = 0; j < 4; ++j) {
                const int d = 2 * ty + i, e = 4 * tx + j;
                sS[d * 65 + e] = acc[i][j] * rs /
                                 (fmaxf(snk[d], EPSV) * fmaxf(snq[e], EPSV));
            }
    }
    __syncthreads();

    // softmax + write attn
    {
        const int w = tid >> 5, lane = tid & 31;
        for (int r = 0; r < 4; ++r) {
            const int d = w * 4 + r;
            float v0 = sS[d * 65 + lane];
            float v1 = sS[d * 65 + 32 + lane];
            float m = fmaxf(v0, v1);
#pragma unroll
            for (int o = 16; o > 0; o >>= 1) m = fmaxf(m, __shfl_xor_sync(0xffffffffu, m, o));
            float e0 = __expf(v0 - m), e1 = __expf(v1 - m);
            float s = e0 + e1;
#pragma unroll
            for (int o = 16; o > 0; o >>= 1) s += __shfl_xor_sync(0xffffffffu, s, o);
            const float inv = 1.f / s;
            e0 *= inv; e1 *= inv;
            sS[d * 65 + lane]      = e0;
            sS[d * 65 + 32 + lane] = e1;
            float* ao = attn_out + (((size_t)(b * NH + h) * DH) + d0 + d) * DH;
            ao[lane]      = e0;
            ao[32 + lane] = e1;
        }
    }
    __syncthreads();

    // reload Wv_h, Wp_h
    for (int r = 0; r < 16; ++r) {
        const int idx = r * 256 + tid;
        const int c = idx >> 6, e = idx & 63;
        sA[c * 65 + e] = Wv[c * INNER + h * 64 + e];
    }
    for (int r = 0; r < 8; ++r) {
        const int idx = r * 256 + tid;
        const int d = idx >> 6, c = idx & 63;
        sB[d * 65 + c] = Wp[(h * 64 + d0 + d) * CCH + c];
    }
    __syncthreads();

    // P = attn^T Wp_h
    {
        float acc[4][4];
#pragma unroll
        for (int i = 0; i < 4; ++i)
#pragma unroll
            for (int j = 0; j < 4; ++j) acc[i][j] = 0.f;
#pragma unroll 4
        for (int dk = 0; dk < 32; ++dk) {
            float a[4], bb[4];
#pragma unroll
            for (int i = 0; i < 4; ++i) a[i]  = sS[dk * 65 + 4 * ty + i];
#pragma unroll
            for (int j = 0; j < 4; ++j) bb[j] = sB[dk * 65 + 4 * tx + j];
#pragma unroll
            for (int i = 0; i < 4; ++i)
#pragma unroll
                for (int j = 0; j < 4; ++j) acc[i][j] = fmaf(a[i], bb[j], acc[i][j]);
        }
#pragma unroll
        for (int i = 0; i < 4; ++i)
#pragma unroll
            for (int j = 0; j < 4; ++j)
                sT[(4 * ty + i) * 65 + 4 * tx + j] = acc[i][j];
    }
    __syncthreads();

    // M += Wv_h @ P
    {
        float acc[4][4];
#pragma unroll
        for (int i = 0; i < 4; ++i)
#pragma unroll
            for (int j = 0; j < 4; ++j) acc[i][j] = 0.f;
#pragma unroll 4
        for (int e = 0; e < 64; ++e) {
            float a[4], bb[4];
#pragma unroll
            for (int i = 0; i < 4; ++i) a[i]  = sA[(4 * ty + i) * 65 + e];
#pragma unroll
            for (int j = 0; j < 4; ++j) bb[j] = sT[e * 65 + 4 * tx + j];
#pragma unroll
            for (int i = 0; i < 4; ++i)
#pragma unroll
                for (int j = 0; j < 4; ++j) acc[i][j] = fmaf(a[i], bb[j], acc[i][j]);
        }
#pragma unroll
        for (int i = 0; i < 4; ++i)
#pragma unroll
            for (int j = 0; j < 4; ++j)
                atomicAdd(&g_M[b * 4096 + (4 * ty + i) * 64 + (4 * tx + j)], acc[i][j]);
    }
}

// ---------------------------------------------------------------------------
// K3: out[b, c, n] = sum_c' x[b, c', n] * M_b[c', c] + bp[c]
// grid = 1024 (4 batches x 256 segments of 64 tokens), FFMA2 micro-kernel.
// M held as duplicated float2 pairs so broadcast operand is a direct LDS.128.
// ---------------------------------------------------------------------------
#define K3_SBYTES (64 * 66 * 8 + 64 * 68 * 4) // dupM + xs = 33792 + 17408 = 51200

__global__ __launch_bounds__(256) void out_kernel(const float* __restrict__ x,
                                                  const float* __restrict__ bp,
                                                  float* __restrict__ out) {
    extern __shared__ char sraw[];
    float2* dupM = reinterpret_cast<float2*>(sraw);          // [64][66] float2
    float*  xs   = reinterpret_cast<float*>(sraw + 64 * 66 * 8); // [64][68]

    const int b   = blockIdx.x >> 8;
    const int seg = blockIdx.x & 255;
    const int nb  = seg * 64;
    const int tid = threadIdx.x;
    const int ty  = tid >> 4;
    const int tx  = tid & 15;

    // load M duplicated: dupM[cp][c] = {M[cp][c], M[cp][c]}
#pragma unroll
    for (int r = 0; r < 4; ++r) {
        const int q    = r * 256 + tid;   // 0..1023
        const int row  = q >> 4;
        const int col4 = q & 15;
        const float4 v = *reinterpret_cast<const float4*>(&g_M[b * 4096 + row * 64 + 4 * col4]);
        float2* d = &dupM[row * 66 + 4 * col4];
        d[0] = make_float2(v.x, v.x);
        d[1] = make_float2(v.y, v.y);
        d[2] = make_float2(v.z, v.z);
        d[3] = make_float2(v.w, v.w);
    }

    const float* xb = x + (size_t)b * CCH * NTOK;
    float* ob = out + (size_t)b * CCH * NTOK;

    // fill xs [c'][n-local] (row-major, conflict-free)
#pragma unroll
    for (int r = 0; r < 4; ++r) {
        const int q    = r * 256 + tid;   // 0..1023
        const int c    = q >> 4;
        const int col4 = q & 15;
        *reinterpret_cast<float4*>(&xs[c * 68 + 4 * col4]) =
            *reinterpret_cast<const float4*>(&xb[c * NTOK + nb + 4 * col4]);
    }
    __syncthreads();

    ull accA[4], accB[4];
#pragma unroll
    for (int i = 0; i < 4; ++i) { accA[i] = 0ull; accB[i] = 0ull; }

#pragma unroll 4
    for (int cp = 0; cp < 64; ++cp) {
        const ulonglong2 ap  = *reinterpret_cast<const ulonglong2*>(&dupM[cp * 66 + 4 * ty]);
        const ulonglong2 ap2 = *reinterpret_cast<const ulonglong2*>(&dupM[cp * 66 + 4 * ty + 2]);
        const ulonglong2 bb  = *reinterpret_cast<const ulonglong2*>(&xs[cp * 68 + 4 * tx]);
        accA[0] = fma2(ap.x,  bb.x, accA[0]); accB[0] = fma2(ap.x,  bb.y, accB[0]);
        accA[1] = fma2(ap.y,  bb.x, accA[1]); accB[1] = fma2(ap.y,  bb.y, accB[1]);
        accA[2] = fma2(ap2.x, bb.x, accA[2]); accB[2] = fma2(ap2.x, bb.y, accB[2]);
        accA[3] = fma2(ap2.y, bb.x, accA[3]); accB[3] = fma2(ap2.y, bb.y, accB[3]);
    }

#pragma unroll
    for (int i = 0; i < 4; ++i) {
        const float bpv = bp[4 * ty + i];
        const float2 lo = up2(accA[i]);
        const float2 hi = up2(accB[i]);
        float4 v;
        v.x = lo.x + bpv; v.y = lo.y + bpv;
        v.z = hi.x + bpv; v.w = hi.y + bpv;
        *reinterpret_cast<float4*>(&ob[(4 * ty + i) * NTOK + nb + 4 * tx]) = v;
    }
}

// ---------------------------------------------------------------------------
extern "C" void kernel_launch(void* const* d_in, const int* in_sizes, int n_in,
                              void* d_out, int out_size) {
    const float* x       = (const float*)d_in[0];
    const float* Wq      = (const float*)d_in[1];
    const float* Wk      = (const float*)d_in[2];
    const float* Wv      = (const float*)d_in[3];
    const float* Wp      = (const float*)d_in[4];
    const float* bp      = (const float*)d_in[5];
    const float* rescale = (const float*)d_in[6];
    float* out      = (float*)d_out;
    float* attn_out = out + OUT_ELEMS;

    cudaFuncSetAttribute(attn_small_kernel,
                         cudaFuncAttributeMaxDynamicSharedMemorySize, K2_SBYTES);
    cudaFuncSetAttribute(out_kernel,
                         cudaFuncAttributeMaxDynamicSharedMemorySize, K3_SBYTES);

    gram_kernel<<<512, 256>>>(x);
    reduce_gram_kernel<<<64, 256>>>();
    attn_small_kernel<<<64, 256, K2_SBYTES>>>(Wq, Wk, Wv, Wp, rescale, attn_out);
    out_kernel<<<1024, 256, K3_SBYTES>>>(x, bp, out);
}

// round 4
// speedup vs baseline: 1.4507x; 1.1429x over previous
#include <cuda_runtime.h>
#include <math.h>

#define NB    4
#define CCH   64
#define NTOK  16384
#define NH    8
#define DH    64
#define INNER 512
#define EPSV  1e-12f

#define OUT_ELEMS  (NB * CCH * NTOK)   // 4194304
#define ATTN_ELEMS (NB * NH * DH * DH) // 131072

typedef unsigned long long ull;

// Scratch (static device globals; no allocation allowed)
__device__ float g_Gpart[512 * CCH * CCH]; // per-group partial Gram matrices
__device__ float g_G[NB * CCH * CCH];      // reduced Gram per batch
__device__ float g_M[NB * CCH * CCH];      // effective 64x64 output matrix per batch

// ---- packed f32x2 helpers (sm_103a FFMA2) ----
__device__ __forceinline__ ull fma2(ull a, ull b, ull c) {
    ull d;
    asm("fma.rn.f32x2 %0, %1, %2, %3;" : "=l"(d) : "l"(a), "l"(b), "l"(c));
    return d;
}
__device__ __forceinline__ ull pk2(float v) {
    ull d;
    asm("mov.b64 %0, {%1, %1};" : "=l"(d) : "f"(v));
    return d;
}
union U2 { ull u; float2 f; };
__device__ __forceinline__ float2 up2(ull v) { U2 t; t.u = v; return t.f; }

// ---------------------------------------------------------------------------
// K1: partial Gram. grid = 256 (4 batches x 64 chunks of 256 tokens).
// Block = 256 threads = 2 independent 128-thread k-groups (128 tokens each).
// Channel-major smem (conflict-free fill); k vectorized along tokens:
// acc pair-folded f32x2. Thread tile 8x4 strided (rows gty+8i, cols gtx+16j).
// ---------------------------------------------------------------------------
#define K1_STRIDE 132
#define K1_SBYTES (2 * 64 * K1_STRIDE * 4) // 67584

__global__ __launch_bounds__(256, 2) void gram_kernel(const float* __restrict__ x) {
    extern __shared__ float xs1[]; // [2][64][K1_STRIDE]
    const int b     = blockIdx.x >> 6;
    const int chunk = blockIdx.x & 63;
    const int tid   = threadIdx.x;
    const int g     = tid >> 7;   // 0..1
    const int t     = tid & 127;
    const int gty   = t >> 4;     // 0..7
    const int gtx   = t & 15;     // 0..15
    const int n0    = chunk * 256 + g * 128;

    float* xg = xs1 + g * 64 * K1_STRIDE;
    const float* xb = x + (size_t)b * CCH * NTOK;

    // fill: 64 ch x 128 tok = 2048 float4 per group, 16 per thread. Coalesced
    // LDG.128, contiguous STS.128 (channel-major).
#pragma unroll
    for (int r = 0; r < 16; ++r) {
        const int q  = r * 128 + t;
        const int c  = q >> 5;
        const int nq = q & 31;
        *reinterpret_cast<float4*>(&xg[c * K1_STRIDE + 4 * nq]) =
            *reinterpret_cast<const float4*>(&xb[c * NTOK + n0 + 4 * nq]);
    }
    __syncthreads();

    ull acc[8][4];
#pragma unroll
    for (int i = 0; i < 8; ++i)
#pragma unroll
        for (int j = 0; j < 4; ++j) acc[i][j] = 0ull;

#pragma unroll 2
    for (int q = 0; q < 32; ++q) {
        ulonglong2 bb[4];
#pragma unroll
        for (int j = 0; j < 4; ++j)
            bb[j] = *reinterpret_cast<const ulonglong2*>(&xg[(gtx + 16 * j) * K1_STRIDE + 4 * q]);
#pragma unroll
        for (int i = 0; i < 8; ++i) {
            const ulonglong2 a =
                *reinterpret_cast<const ulonglong2*>(&xg[(gty + 8 * i) * K1_STRIDE + 4 * q]);
#pragma unroll
            for (int j = 0; j < 4; ++j) {
                acc[i][j] = fma2(a.x, bb[j].x, acc[i][j]);
                acc[i][j] = fma2(a.y, bb[j].y, acc[i][j]);
            }
        }
    }

    float* gp = g_Gpart + ((size_t)blockIdx.x * 2 + g) * 4096;
#pragma unroll
    for (int i = 0; i < 8; ++i)
#pragma unroll
        for (int j = 0; j < 4; ++j) {
            const float2 f = up2(acc[i][j]);
            gp[(gty + 8 * i) * 64 + (gtx + 16 * j)] = f.x + f.y;
        }
}

// ---------------------------------------------------------------------------
// K1b: reduce 128 partials per batch into g_G; also zero g_M.
// ---------------------------------------------------------------------------
__global__ __launch_bounds__(256) void reduce_gram_kernel() {
    const int i = blockIdx.x * 256 + threadIdx.x; // 0..16383
    const int b = i >> 12;
    const int idx = i & 4095;
    float s = 0.f;
    const float* gp = g_Gpart + (size_t)(b * 128) * 4096 + idx;
#pragma unroll 8
    for (int p = 0; p < 128; ++p) s += gp[(size_t)p * 4096];
    g_G[i] = s;
    g_M[i] = 0.f;
}

// ---------------------------------------------------------------------------
// K2: per (batch, head, d-half) attention math. (unchanged)
// ---------------------------------------------------------------------------
#define K2_SFLOATS 19072
#define K2_SBYTES  (K2_SFLOATS * 4)

__global__ __launch_bounds__(256) void attn_small_kernel(
    const float* __restrict__ Wq, const float* __restrict__ Wk,
    const float* __restrict__ Wv, const float* __restrict__ Wp,
    const float* __restrict__ rescale, float* __restrict__ attn_out) {
    extern __shared__ float smem[];
    float* sG  = smem;          // 64x65 : Gram
    float* sA  = smem + 4160;   // 64x65 : Wq_h, later Wv_h
    float* sB  = smem + 8320;   // 64x65 : Wk_h, later Wp_h (32 rows)
    float* sT  = smem + 12480;  // 64x65 : T1 = G@Wq_h, later P
    float* sS  = smem + 16640;  // 32x65 : T2t, later attn logits/probs
    float* red = smem + 18720;  // 256 scratch
    float* snq = smem + 18976;  // 64
    float* snk = smem + 19040;  // 32

    const int bx   = blockIdx.x;
    const int b    = bx >> 4;
    const int h    = (bx >> 1) & 7;
    const int half = bx & 1;
    const int d0   = half * 32;
    const int tid  = threadIdx.x;
    const int ty   = tid >> 4;
    const int tx   = tid & 15;

    for (int r = 0; r < 16; ++r) {
        const int idx = r * 256 + tid;
        const int c = idx >> 6, c2 = idx & 63;
        sG[c * 65 + c2] = g_G[b * 4096 + idx];
        sA[c * 65 + c2] = Wq[c * INNER + h * 64 + c2];
        sB[c * 65 + c2] = Wk[c * INNER + h * 64 + c2];
    }
    __syncthreads();

    // T1 = G @ Wq_h
    {
        float acc[4][4];
#pragma unroll
        for (int i = 0; i < 4; ++i)
#pragma unroll
            for (int j = 0; j < 4; ++j) acc[i][j] = 0.f;
#pragma unroll 4
        for (int cp = 0; cp < 64; ++cp) {
            float a[4], bb[4];
#pragma unroll
            for (int i = 0; i < 4; ++i) a[i]  = sG[(4 * ty + i) * 65 + cp];
#pragma unroll
            for (int j = 0; j < 4; ++j) bb[j] = sA[cp * 65 + 4 * tx + j];
#pragma unroll
            for (int i = 0; i < 4; ++i)
#pragma unroll
                for (int j = 0; j < 4; ++j) acc[i][j] = fmaf(a[i], bb[j], acc[i][j]);
        }
#pragma unroll
        for (int i = 0; i < 4; ++i)
#pragma unroll
            for (int j = 0; j < 4; ++j)
                sT[(4 * ty + i) * 65 + 4 * tx + j] = acc[i][j];
    }
    __syncthreads();

    // nq
    {
        const int e = tid & 63, p = tid >> 6;
        float s = 0.f;
        for (int c = p * 16; c < p * 16 + 16; ++c) s += sA[c * 65 + e] * sT[c * 65 + e];
        red[p * 64 + e] = s;
    }
    __syncthreads();
    if (tid < 64) snq[tid] = sqrtf(red[tid] + red[64 + tid] + red[128 + tid] + red[192 + tid]);
    __syncthreads();

    // T2t = Wk_h^T G (32x64)
    {
        float acc[2][4] = {{0.f, 0.f, 0.f, 0.f}, {0.f, 0.f, 0.f, 0.f}};
#pragma unroll 4
        for (int cp = 0; cp < 64; ++cp) {
            float a[2], bb[4];
#pragma unroll
            for (int i = 0; i < 2; ++i) a[i]  = sB[cp * 65 + d0 + 2 * ty + i];
#pragma unroll
            for (int j = 0; j < 4; ++j) bb[j] = sG[cp * 65 + 4 * tx + j];
#pragma unroll
            for (int i = 0; i < 2; ++i)
#pragma unroll
                for (int j = 0; j < 4; ++j) acc[i][j] = fmaf(a[i], bb[j], acc[i][j]);
        }
#pragma unroll
        for (int i = 0; i < 2; ++i)
#pragma unroll
            for (int j = 0; j < 4; ++j)
                sS[(2 * ty + i) * 65 + 4 * tx + j] = acc[i][j];
    }
    __syncthreads();

    // nk
    {
        const int d = tid & 31, p = tid >> 5;
        float s = 0.f;
        for (int c = p * 8; c < p * 8 + 8; ++c) s += sB[c * 65 + d0 + d] * sS[d * 65 + c];
        red[p * 32 + d] = s;
    }
    __syncthreads();
    if (tid < 32) {
        float s = 0.f;
#pragma unroll
        for (int p = 0; p < 8; ++p) s += red[p * 32 + tid];
        snk[tid] = sqrtf(s);
    }
    __syncthreads();

    // logits
    {
        float acc[2][4] = {{0.f, 0.f, 0.f, 0.f}, {0.f, 0.f, 0.f, 0.f}};
#pragma unroll 4
        for (int cp = 0; cp < 64; ++cp) {
            float a[2], bb[4];
#pragma unroll
            for (int i = 0; i < 2; ++i) a[i]  = sB[cp * 65 + d0 + 2 * ty + i];
#pragma unroll
            for (int j = 0; j < 4; ++j) bb[j] = sT[cp * 65 + 4 * tx + j];
#pragma unroll
            for (int i = 0; i < 2; ++i)
#pragma unroll
                for (int j = 0; j < 4; ++j) acc[i][j] = fmaf(a[i], bb[j], acc[i][j]);
        }
        const float rs = rescale[h];
#pragma unroll
        for (int i = 0; i < 2; ++i)
#pragma unroll
            for (int j = 0; j < 4; ++j) {
                const int d = 2 * ty + i, e = 4 * tx + j;
                sS[d * 65 + e] = acc[i][j] * rs /
                                 (fmaxf(snk[d], EPSV) * fmaxf(snq[e], EPSV));
            }
    }
    __syncthreads();

    // softmax + write attn
    {
        const int w = tid >> 5, lane = tid & 31;
        for (int r = 0; r < 4; ++r) {
            const int d = w * 4 + r;
            float v0 = sS[d * 65 + lane];
            float v1 = sS[d * 65 + 32 + lane];
            float m = fmaxf(v0, v1);
#pragma unroll
            for (int o = 16; o > 0; o >>= 1) m = fmaxf(m, __shfl_xor_sync(0xffffffffu, m, o));
            float e0 = __expf(v0 - m), e1 = __expf(v1 - m);
            float s = e0 + e1;
#pragma unroll
            for (int o = 16; o > 0; o >>= 1) s += __shfl_xor_sync(0xffffffffu, s, o);
            const float inv = 1.f / s;
            e0 *= inv; e1 *= inv;
            sS[d * 65 + lane]      = e0;
            sS[d * 65 + 32 + lane] = e1;
            float* ao = attn_out + (((size_t)(b * NH + h) * DH) + d0 + d) * DH;
            ao[lane]      = e0;
            ao[32 + lane] = e1;
        }
    }
    __syncthreads();

    // reload Wv_h, Wp_h
    for (int r = 0; r < 16; ++r) {
        const int idx = r * 256 + tid;
        const int c = idx >> 6, e = idx & 63;
        sA[c * 65 + e] = Wv[c * INNER + h * 64 + e];
    }
    for (int r = 0; r < 8; ++r) {
        const int idx = r * 256 + tid;
        const int d = idx >> 6, c = idx & 63;
        sB[d * 65 + c] = Wp[(h * 64 + d0 + d) * CCH + c];
    }
    __syncthreads();

    // P = attn^T Wp_h
    {
        float acc[4][4];
#pragma unroll
        for (int i = 0; i < 4; ++i)
#pragma unroll
            for (int j = 0; j < 4; ++j) acc[i][j] = 0.f;
#pragma unroll 4
        for (int dk = 0; dk < 32; ++dk) {
            float a[4], bb[4];
#pragma unroll
            for (int i = 0; i < 4; ++i) a[i]  = sS[dk * 65 + 4 * ty + i];
#pragma unroll
            for (int j = 0; j < 4; ++j) bb[j] = sB[dk * 65 + 4 * tx + j];
#pragma unroll
            for (int i = 0; i < 4; ++i)
#pragma unroll
                for (int j = 0; j < 4; ++j) acc[i][j] = fmaf(a[i], bb[j], acc[i][j]);
        }
#pragma unroll
        for (int i = 0; i < 4; ++i)
#pragma unroll
            for (int j = 0; j < 4; ++j)
                sT[(4 * ty + i) * 65 + 4 * tx + j] = acc[i][j];
    }
    __syncthreads();

    // M += Wv_h @ P
    {
        float acc[4][4];
#pragma unroll
        for (int i = 0; i < 4; ++i)
#pragma unroll
            for (int j = 0; j < 4; ++j) acc[i][j] = 0.f;
#pragma unroll 4
        for (int e = 0; e < 64; ++e) {
            float a[4], bb[4];
#pragma unroll
            for (int i = 0; i < 4; ++i) a[i]  = sA[(4 * ty + i) * 65 + e];
#pragma unroll
            for (int j = 0; j < 4; ++j) bb[j] = sT[e * 65 + 4 * tx + j];
#pragma unroll
            for (int i = 0; i < 4; ++i)
#pragma unroll
                for (int j = 0; j < 4; ++j) acc[i][j] = fmaf(a[i], bb[j], acc[i][j]);
        }
#pragma unroll
        for (int i = 0; i < 4; ++i)
#pragma unroll
            for (int j = 0; j < 4; ++j)
                atomicAdd(&g_M[b * 4096 + (4 * ty + i) * 64 + (4 * tx + j)], acc[i][j]);
    }
}

// ---------------------------------------------------------------------------
// K3: out[b, c, n] = sum_cp x[b, cp, n] * M_b[cp, c] + bp[c]
// grid = 512 (4 batches x 128 segments of 128 tokens), 128 threads.
// Thread tile 8 ch x 8 tok (strided quads); M float4 + pk2 (ALU pipe).
// ---------------------------------------------------------------------------
#define K3_STRIDE 132
#define K3_SBYTES (64 * K3_STRIDE * 4 + 4096 * 4) // 33792 + 16384 = 50176

__global__ __launch_bounds__(128, 2) void out_kernel(const float* __restrict__ x,
                                                     const float* __restrict__ bp,
                                                     float* __restrict__ out) {
    extern __shared__ float sm3[];
    float* xs = sm3;                      // [64][K3_STRIDE]
    float* sM = sm3 + 64 * K3_STRIDE;     // [64][64] = M[cp][c]

    const int b   = blockIdx.x >> 7;
    const int seg = blockIdx.x & 127;
    const int nb  = seg * 128;
    const int tid = threadIdx.x;
    const int ty  = tid >> 4;   // 0..7  -> channels 8ty..8ty+7
    const int tx  = tid & 15;   // 0..15 -> token quads tx, tx+16

    const float* xb = x + (size_t)b * CCH * NTOK;
    float* ob = out + (size_t)b * CCH * NTOK;

    // fill M (1024 f4 / 128 thr = 8 each)
#pragma unroll
    for (int r = 0; r < 8; ++r) {
        const int q = r * 128 + tid;
        *reinterpret_cast<float4*>(&sM[4 * q]) =
            *reinterpret_cast<const float4*>(&g_M[b * 4096 + 4 * q]);
    }
    // fill xs (64 ch x 128 tok = 2048 f4 / 128 thr = 16 each), channel-major
#pragma unroll
    for (int r = 0; r < 16; ++r) {
        const int q  = r * 128 + tid;
        const int c  = q >> 5;
        const int nq = q & 31;
        *reinterpret_cast<float4*>(&xs[c * K3_STRIDE + 4 * nq]) =
            *reinterpret_cast<const float4*>(&xb[c * NTOK + nb + 4 * nq]);
    }
    __syncthreads();

    ull acc[8][2][2]; // [channel i][quad j][pair p]
#pragma unroll
    for (int i = 0; i < 8; ++i)
#pragma unroll
        for (int j = 0; j < 2; ++j) { acc[i][j][0] = 0ull; acc[i][j][1] = 0ull; }

#pragma unroll 2
    for (int cp = 0; cp < 64; ++cp) {
        // b operands: two strided token quads
        ulonglong2 bb[2];
#pragma unroll
        for (int j = 0; j < 2; ++j)
            bb[j] = *reinterpret_cast<const ulonglong2*>(&xs[cp * K3_STRIDE + 4 * (tx + 16 * j)]);
        // a operands: 8 M values, packed
        const float4 m0 = *reinterpret_cast<const float4*>(&sM[cp * 64 + 8 * ty]);
        const float4 m1 = *reinterpret_cast<const float4*>(&sM[cp * 64 + 8 * ty + 4]);
        const ull a0 = pk2(m0.x), a1 = pk2(m0.y), a2 = pk2(m0.z), a3 = pk2(m0.w);
        const ull a4 = pk2(m1.x), a5 = pk2(m1.y), a6 = pk2(m1.z), a7 = pk2(m1.w);
        const ull av[8] = {a0, a1, a2, a3, a4, a5, a6, a7};
#pragma unroll
        for (int i = 0; i < 8; ++i)
#pragma unroll
            for (int j = 0; j < 2; ++j) {
                acc[i][j][0] = fma2(av[i], bb[j].x, acc[i][j][0]);
                acc[i][j][1] = fma2(av[i], bb[j].y, acc[i][j][1]);
            }
    }

#pragma unroll
    for (int i = 0; i < 8; ++i) {
        const float bpv = bp[8 * ty + i];
#pragma unroll
        for (int j = 0; j < 2; ++j) {
            const float2 lo = up2(acc[i][j][0]);
            const float2 hi = up2(acc[i][j][1]);
            float4 v;
            v.x = lo.x + bpv; v.y = lo.y + bpv;
            v.z = hi.x + bpv; v.w = hi.y + bpv;
            *reinterpret_cast<float4*>(&ob[(8 * ty + i) * NTOK + nb + 4 * (tx + 16 * j)]) = v;
        }
    }
}

// ---------------------------------------------------------------------------
extern "C" void kernel_launch(void* const* d_in, const int* in_sizes, int n_in,
                              void* d_out, int out_size) {
    const float* x       = (const float*)d_in[0];
    const float* Wq      = (const float*)d_in[1];
    const float* Wk      = (const float*)d_in[2];
    const float* Wv      = (const float*)d_in[3];
    const float* Wp      = (const float*)d_in[4];
    const float* bp      = (const float*)d_in[5];
    const float* rescale = (const float*)d_in[6];
    float* out      = (float*)d_out;
    float* attn_out = out + OUT_ELEMS;

    cudaFuncSetAttribute(gram_kernel,
                         cudaFuncAttributeMaxDynamicSharedMemorySize, K1_SBYTES);
    cudaFuncSetAttribute(attn_small_kernel,
                         cudaFuncAttributeMaxDynamicSharedMemorySize, K2_SBYTES);
    cudaFuncSetAttribute(out_kernel,
                         cudaFuncAttributeMaxDynamicSharedMemorySize, K3_SBYTES);

    gram_kernel<<<256, 256, K1_SBYTES>>>(x);
    reduce_gram_kernel<<<64, 256>>>();
    attn_small_kernel<<<64, 256, K2_SBYTES>>>(Wq, Wk, Wv, Wp, rescale, attn_out);
    out_kernel<<<512, 128, K3_SBYTES>>>(x, bp, out);
}

// round 5
// speedup vs baseline: 1.4541x; 1.0024x over previous
#include <cuda_runtime.h>
#include <math.h>

#define NB    4
#define CCH   64
#define NTOK  16384
#define NH    8
#define DH    64
#define INNER 512
#define EPSV  1e-12f

#define OUT_ELEMS  (NB * CCH * NTOK)   // 4194304
#define ATTN_ELEMS (NB * NH * DH * DH) // 131072

typedef unsigned long long ull;

// Scratch (static device globals; no allocation allowed)
__device__ float g_Gpart[512 * CCH * CCH]; // per-group partial Gram matrices
__device__ float g_G[NB * CCH * CCH];      // reduced Gram per batch
__device__ float g_M[NB * CCH * CCH];      // effective 64x64 output matrix per batch

// ---- packed f32x2 helpers (sm_103a FFMA2) ----
__device__ __forceinline__ ull fma2(ull a, ull b, ull c) {
    ull d;
    asm("fma.rn.f32x2 %0, %1, %2, %3;" : "=l"(d) : "l"(a), "l"(b), "l"(c));
    return d;
}
__device__ __forceinline__ ull pk2(float v) {
    ull d;
    asm("mov.b64 %0, {%1, %1};" : "=l"(d) : "f"(v));
    return d;
}
union U2 { ull u; float2 f; };
__device__ __forceinline__ float2 up2(ull v) { U2 t; t.u = v; return t.f; }

// ---------------------------------------------------------------------------
// K1: partial Gram. grid = 256 (4 batches x 64 chunks of 256 tokens).
// Block = 256 threads = 2 independent 128-thread k-groups (128 tokens each).
// ---------------------------------------------------------------------------
#define K1_STRIDE 132
#define K1_SBYTES (2 * 64 * K1_STRIDE * 4) // 67584

__global__ __launch_bounds__(256, 2) void gram_kernel(const float* __restrict__ x) {
    extern __shared__ float xs1[]; // [2][64][K1_STRIDE]
    const int b     = blockIdx.x >> 6;
    const int chunk = blockIdx.x & 63;
    const int tid   = threadIdx.x;
    const int g     = tid >> 7;   // 0..1
    const int t     = tid & 127;
    const int gty   = t >> 4;     // 0..7
    const int gtx   = t & 15;     // 0..15
    const int n0    = chunk * 256 + g * 128;

    float* xg = xs1 + g * 64 * K1_STRIDE;
    const float* xb = x + (size_t)b * CCH * NTOK;

#pragma unroll
    for (int r = 0; r < 16; ++r) {
        const int q  = r * 128 + t;
        const int c  = q >> 5;
        const int nq = q & 31;
        *reinterpret_cast<float4*>(&xg[c * K1_STRIDE + 4 * nq]) =
            *reinterpret_cast<const float4*>(&xb[c * NTOK + n0 + 4 * nq]);
    }
    __syncthreads();

    ull acc[8][4];
#pragma unroll
    for (int i = 0; i < 8; ++i)
#pragma unroll
        for (int j = 0; j < 4; ++j) acc[i][j] = 0ull;

#pragma unroll 2
    for (int q = 0; q < 32; ++q) {
        ulonglong2 bb[4];
#pragma unroll
        for (int j = 0; j < 4; ++j)
            bb[j] = *reinterpret_cast<const ulonglong2*>(&xg[(gtx + 16 * j) * K1_STRIDE + 4 * q]);
#pragma unroll
        for (int i = 0; i < 8; ++i) {
            const ulonglong2 a =
                *reinterpret_cast<const ulonglong2*>(&xg[(gty + 8 * i) * K1_STRIDE + 4 * q]);
#pragma unroll
            for (int j = 0; j < 4; ++j) {
                acc[i][j] = fma2(a.x, bb[j].x, acc[i][j]);
                acc[i][j] = fma2(a.y, bb[j].y, acc[i][j]);
            }
        }
    }

    float* gp = g_Gpart + ((size_t)blockIdx.x * 2 + g) * 4096;
#pragma unroll
    for (int i = 0; i < 8; ++i)
#pragma unroll
        for (int j = 0; j < 4; ++j) {
            const float2 f = up2(acc[i][j]);
            gp[(gty + 8 * i) * 64 + (gtx + 16 * j)] = f.x + f.y;
        }
}

// ---------------------------------------------------------------------------
// K1b: reduce 128 partials per batch into g_G; also zero g_M.
// ---------------------------------------------------------------------------
__global__ __launch_bounds__(256) void reduce_gram_kernel() {
    const int i = blockIdx.x * 256 + threadIdx.x; // 0..16383
    const int b = i >> 12;
    const int idx = i & 4095;
    float s = 0.f;
    const float* gp = g_Gpart + (size_t)(b * 128) * 4096 + idx;
#pragma unroll 8
    for (int p = 0; p < 128; ++p) s += gp[(size_t)p * 4096];
    g_G[i] = s;
    g_M[i] = 0.f;
}

// ---------------------------------------------------------------------------
// K2: per (batch, head, d-half) attention math. (unchanged)
// ---------------------------------------------------------------------------
#define K2_SFLOATS 19072
#define K2_SBYTES  (K2_SFLOATS * 4)

__global__ __launch_bounds__(256) void attn_small_kernel(
    const float* __restrict__ Wq, const float* __restrict__ Wk,
    const float* __restrict__ Wv, const float* __restrict__ Wp,
    const float* __restrict__ rescale, float* __restrict__ attn_out) {
    extern __shared__ float smem[];
    float* sG  = smem;          // 64x65 : Gram
    float* sA  = smem + 4160;   // 64x65 : Wq_h, later Wv_h
    float* sB  = smem + 8320;   // 64x65 : Wk_h, later Wp_h (32 rows)
    float* sT  = smem + 12480;  // 64x65 : T1 = G@Wq_h, later P
    float* sS  = smem + 16640;  // 32x65 : T2t, later attn logits/probs
    float* red = smem + 18720;  // 256 scratch
    float* snq = smem + 18976;  // 64
    float* snk = smem + 19040;  // 32

    const int bx   = blockIdx.x;
    const int b    = bx >> 4;
    const int h    = (bx >> 1) & 7;
    const int half = bx & 1;
    const int d0   = half * 32;
    const int tid  = threadIdx.x;
    const int ty   = tid >> 4;
    const int tx   = tid & 15;

    for (int r = 0; r < 16; ++r) {
        const int idx = r * 256 + tid;
        const int c = idx >> 6, c2 = idx & 63;
        sG[c * 65 + c2] = g_G[b * 4096 + idx];
        sA[c * 65 + c2] = Wq[c * INNER + h * 64 + c2];
        sB[c * 65 + c2] = Wk[c * INNER + h * 64 + c2];
    }
    __syncthreads();

    // T1 = G @ Wq_h
    {
        float acc[4][4];
#pragma unroll
        for (int i = 0; i < 4; ++i)
#pragma unroll
            for (int j = 0; j < 4; ++j) acc[i][j] = 0.f;
#pragma unroll 4
        for (int cp = 0; cp < 64; ++cp) {
            float a[4], bb[4];
#pragma unroll
            for (int i = 0; i < 4; ++i) a[i]  = sG[(4 * ty + i) * 65 + cp];
#pragma unroll
            for (int j = 0; j < 4; ++j) bb[j] = sA[cp * 65 + 4 * tx + j];
#pragma unroll
            for (int i = 0; i < 4; ++i)
#pragma unroll
                for (int j = 0; j < 4; ++j) acc[i][j] = fmaf(a[i], bb[j], acc[i][j]);
        }
#pragma unroll
        for (int i = 0; i < 4; ++i)
#pragma unroll
            for (int j = 0; j < 4; ++j)
                sT[(4 * ty + i) * 65 + 4 * tx + j] = acc[i][j];
    }
    __syncthreads();

    // nq
    {
        const int e = tid & 63, p = tid >> 6;
        float s = 0.f;
        for (int c = p * 16; c < p * 16 + 16; ++c) s += sA[c * 65 + e] * sT[c * 65 + e];
        red[p * 64 + e] = s;
    }
    __syncthreads();
    if (tid < 64) snq[tid] = sqrtf(red[tid] + red[64 + tid] + red[128 + tid] + red[192 + tid]);
    __syncthreads();

    // T2t = Wk_h^T G (32x64)
    {
        float acc[2][4] = {{0.f, 0.f, 0.f, 0.f}, {0.f, 0.f, 0.f, 0.f}};
#pragma unroll 4
        for (int cp = 0; cp < 64; ++cp) {
            float a[2], bb[4];
#pragma unroll
            for (int i = 0; i < 2; ++i) a[i]  = sB[cp * 65 + d0 + 2 * ty + i];
#pragma unroll
            for (int j = 0; j < 4; ++j) bb[j] = sG[cp * 65 + 4 * tx + j];
#pragma unroll
            for (int i = 0; i < 2; ++i)
#pragma unroll
                for (int j = 0; j < 4; ++j) acc[i][j] = fmaf(a[i], bb[j], acc[i][j]);
        }
#pragma unroll
        for (int i = 0; i < 2; ++i)
#pragma unroll
            for (int j = 0; j < 4; ++j)
                sS[(2 * ty + i) * 65 + 4 * tx + j] = acc[i][j];
    }
    __syncthreads();

    // nk
    {
        const int d = tid & 31, p = tid >> 5;
        float s = 0.f;
        for (int c = p * 8; c < p * 8 + 8; ++c) s += sB[c * 65 + d0 + d] * sS[d * 65 + c];
        red[p * 32 + d] = s;
    }
    __syncthreads();
    if (tid < 32) {
        float s = 0.f;
#pragma unroll
        for (int p = 0; p < 8; ++p) s += red[p * 32 + tid];
        snk[tid] = sqrtf(s);
    }
    __syncthreads();

    // logits
    {
        float acc[2][4] = {{0.f, 0.f, 0.f, 0.f}, {0.f, 0.f, 0.f, 0.f}};
#pragma unroll 4
        for (int cp = 0; cp < 64; ++cp) {
            float a[2], bb[4];
#pragma unroll
            for (int i = 0; i < 2; ++i) a[i]  = sB[cp * 65 + d0 + 2 * ty + i];
#pragma unroll
            for (int j = 0; j < 4; ++j) bb[j] = sT[cp * 65 + 4 * tx + j];
#pragma unroll
            for (int i = 0; i < 2; ++i)
#pragma unroll
                for (int j = 0; j < 4; ++j) acc[i][j] = fmaf(a[i], bb[j], acc[i][j]);
        }
        const float rs = rescale[h];
#pragma unroll
        for (int i = 0; i < 2; ++i)
#pragma unroll
            for (int j = 0; j < 4; ++j) {
                const int d = 2 * ty + i, e = 4 * tx + j;
                sS[d * 65 + e] = acc[i][j] * rs /
                                 (fmaxf(snk[d], EPSV) * fmaxf(snq[e], EPSV));
            }
    }
    __syncthreads();

    // softmax + write attn
    {
        const int w = tid >> 5, lane = tid & 31;
        for (int r = 0; r < 4; ++r) {
            const int d = w * 4 + r;
            float v0 = sS[d * 65 + lane];
            float v1 = sS[d * 65 + 32 + lane];
            float m = fmaxf(v0, v1);
#pragma unroll
            for (int o = 16; o > 0; o >>= 1) m = fmaxf(m, __shfl_xor_sync(0xffffffffu, m, o));
            float e0 = __expf(v0 - m), e1 = __expf(v1 - m);
            float s = e0 + e1;
#pragma unroll
            for (int o = 16; o > 0; o >>= 1) s += __shfl_xor_sync(0xffffffffu, s, o);
            const float inv = 1.f / s;
            e0 *= inv; e1 *= inv;
            sS[d * 65 + lane]      = e0;
            sS[d * 65 + 32 + lane] = e1;
            float* ao = attn_out + (((size_t)(b * NH + h) * DH) + d0 + d) * DH;
            ao[lane]      = e0;
            ao[32 + lane] = e1;
        }
    }
    __syncthreads();

    // reload Wv_h, Wp_h
    for (int r = 0; r < 16; ++r) {
        const int idx = r * 256 + tid;
        const int c = idx >> 6, e = idx & 63;
        sA[c * 65 + e] = Wv[c * INNER + h * 64 + e];
    }
    for (int r = 0; r < 8; ++r) {
        const int idx = r * 256 + tid;
        const int d = idx >> 6, c = idx & 63;
        sB[d * 65 + c] = Wp[(h * 64 + d0 + d) * CCH + c];
    }
    __syncthreads();

    // P = attn^T Wp_h
    {
        float acc[4][4];
#pragma unroll
        for (int i = 0; i < 4; ++i)
#pragma unroll
            for (int j = 0; j < 4; ++j) acc[i][j] = 0.f;
#pragma unroll 4
        for (int dk = 0; dk < 32; ++dk) {
            float a[4], bb[4];
#pragma unroll
            for (int i = 0; i < 4; ++i) a[i]  = sS[dk * 65 + 4 * ty + i];
#pragma unroll
            for (int j = 0; j < 4; ++j) bb[j] = sB[dk * 65 + 4 * tx + j];
#pragma unroll
            for (int i = 0; i < 4; ++i)
#pragma unroll
                for (int j = 0; j < 4; ++j) acc[i][j] = fmaf(a[i], bb[j], acc[i][j]);
        }
#pragma unroll
        for (int i = 0; i < 4; ++i)
#pragma unroll
            for (int j = 0; j < 4; ++j)
                sT[(4 * ty + i) * 65 + 4 * tx + j] = acc[i][j];
    }
    __syncthreads();

    // M += Wv_h @ P
    {
        float acc[4][4];
#pragma unroll
        for (int i = 0; i < 4; ++i)
#pragma unroll
            for (int j = 0; j < 4; ++j) acc[i][j] = 0.f;
#pragma unroll 4
        for (int e = 0; e < 64; ++e) {
            float a[4], bb[4];
#pragma unroll
            for (int i = 0; i < 4; ++i) a[i]  = sA[(4 * ty + i) * 65 + e];
#pragma unroll
            for (int j = 0; j < 4; ++j) bb[j] = sT[e * 65 + 4 * tx + j];
#pragma unroll
            for (int i = 0; i < 4; ++i)
#pragma unroll
                for (int j = 0; j < 4; ++j) acc[i][j] = fmaf(a[i], bb[j], acc[i][j]);
        }
#pragma unroll
        for (int i = 0; i < 4; ++i)
#pragma unroll
            for (int j = 0; j < 4; ++j)
                atomicAdd(&g_M[b * 4096 + (4 * ty + i) * 64 + (4 * tx + j)], acc[i][j]);
    }
}

// ---------------------------------------------------------------------------
// K3: out[b, c, n] = sum_cp x[b, cp, n] * M_b[cp, c] + bp[c]
// grid = 256 (4 batches x 64 segments of 256 tokens), 256 threads.
// Thread tile 8 ch x 8 tok. Warp = one ty group -> M loads are broadcast.
// ---------------------------------------------------------------------------
#define K3_STRIDE 260
#define K3_SBYTES (64 * K3_STRIDE * 4 + 4096 * 4) // 66560 + 16384 = 82944

__global__ __launch_bounds__(256, 2) void out_kernel(const float* __restrict__ x,
                                                     const float* __restrict__ bp,
                                                     float* __restrict__ out) {
    extern __shared__ float sm3[];
    float* xs = sm3;                      // [64][K3_STRIDE]
    float* sM = sm3 + 64 * K3_STRIDE;     // [64][64] = M[cp][c]

    const int b   = blockIdx.x >> 6;
    const int seg = blockIdx.x & 63;
    const int nb  = seg * 256;
    const int tid = threadIdx.x;
    const int ty  = tid >> 5;   // 0..7  -> channels 8ty..8ty+7 (warp-uniform)
    const int tx  = tid & 31;   // 0..31 -> token quads tx, tx+32

    const float* xb = x + (size_t)b * CCH * NTOK;
    float* ob = out + (size_t)b * CCH * NTOK;

    // fill M (1024 f4 / 256 thr = 4 each)
#pragma unroll
    for (int r = 0; r < 4; ++r) {
        const int q = r * 256 + tid;
        *reinterpret_cast<float4*>(&sM[4 * q]) =
            *reinterpret_cast<const float4*>(&g_M[b * 4096 + 4 * q]);
    }
    // fill xs (64 ch x 256 tok = 4096 f4 / 256 thr = 16 each), channel-major
#pragma unroll
    for (int r = 0; r < 16; ++r) {
        const int q  = r * 256 + tid;
        const int c  = q >> 6;
        const int nq = q & 63;
        *reinterpret_cast<float4*>(&xs[c * K3_STRIDE + 4 * nq]) =
            *reinterpret_cast<const float4*>(&xb[c * NTOK + nb + 4 * nq]);
    }
    __syncthreads();

    ull acc[8][2][2]; // [channel i][quad j][pair p]
#pragma unroll
    for (int i = 0; i < 8; ++i)
#pragma unroll
        for (int j = 0; j < 2; ++j) { acc[i][j][0] = 0ull; acc[i][j][1] = 0ull; }

#pragma unroll 2
    for (int cp = 0; cp < 64; ++cp) {
        // b operands: two strided token quads (conflict-free LDS.128)
        ulonglong2 bb[2];
#pragma unroll
        for (int j = 0; j < 2; ++j)
            bb[j] = *reinterpret_cast<const ulonglong2*>(&xs[cp * K3_STRIDE + 4 * (tx + 32 * j)]);
        // a operands: 8 M values (warp-broadcast LDS.128 x2), packed via ALU pipe
        const float4 m0 = *reinterpret_cast<const float4*>(&sM[cp * 64 + 8 * ty]);
        const float4 m1 = *reinterpret_cast<const float4*>(&sM[cp * 64 + 8 * ty + 4]);
        const ull av[8] = {pk2(m0.x), pk2(m0.y), pk2(m0.z), pk2(m0.w),
                           pk2(m1.x), pk2(m1.y), pk2(m1.z), pk2(m1.w)};
#pragma unroll
        for (int i = 0; i < 8; ++i)
#pragma unroll
            for (int j = 0; j < 2; ++j) {
                acc[i][j][0] = fma2(av[i], bb[j].x, acc[i][j][0]);
                acc[i][j][1] = fma2(av[i], bb[j].y, acc[i][j][1]);
            }
    }

#pragma unroll
    for (int i = 0; i < 8; ++i) {
        const float bpv = bp[8 * ty + i];
#pragma unroll
        for (int j = 0; j < 2; ++j) {
            const float2 lo = up2(acc[i][j][0]);
            const float2 hi = up2(acc[i][j][1]);
            float4 v;
            v.x = lo.x + bpv; v.y = lo.y + bpv;
            v.z = hi.x + bpv; v.w = hi.y + bpv;
            *reinterpret_cast<float4*>(&ob[(8 * ty + i) * NTOK + nb + 4 * (tx + 32 * j)]) = v;
        }
    }
}

// ---------------------------------------------------------------------------
extern "C" void kernel_launch(void* const* d_in, const int* in_sizes, int n_in,
                              void* d_out, int out_size) {
    const float* x       = (const float*)d_in[0];
    const float* Wq      = (const float*)d_in[1];
    const float* Wk      = (const float*)d_in[2];
    const float* Wv      = (const float*)d_in[3];
    const float* Wp      = (const float*)d_in[4];
    const float* bp      = (const float*)d_in[5];
    const float* rescale = (const float*)d_in[6];
    float* out      = (float*)d_out;
    float* attn_out = out + OUT_ELEMS;

    cudaFuncSetAttribute(gram_kernel,
                         cudaFuncAttributeMaxDynamicSharedMemorySize, K1_SBYTES);
    cudaFuncSetAttribute(attn_small_kernel,
                         cudaFuncAttributeMaxDynamicSharedMemorySize, K2_SBYTES);
    cudaFuncSetAttribute(out_kernel,
                         cudaFuncAttributeMaxDynamicSharedMemorySize, K3_SBYTES);

    gram_kernel<<<256, 256, K1_SBYTES>>>(x);
    reduce_gram_kernel<<<64, 256>>>();
    attn_small_kernel<<<64, 256, K2_SBYTES>>>(Wq, Wk, Wv, Wp, rescale, attn_out);
    out_kernel<<<256, 256, K3_SBYTES>>>(x, bp, out);
}

// round 6
// speedup vs baseline: 1.8863x; 1.2972x over previous
#include <cuda_runtime.h>
#include <cuda_bf16.h>
#include <math.h>

#define NB    4
#define CCH   64
#define NTOK  16384
#define NH    8
#define DH    64
#define INNER 512
#define EPSV  1e-12f

#define OUT_ELEMS  (NB * CCH * NTOK)   // 4194304
#define ATTN_ELEMS (NB * NH * DH * DH) // 131072

// Scratch (static device globals; no allocation allowed)
__device__ float g_Gpart[256 * CCH * CCH]; // per-block partial Gram matrices
__device__ float g_G[NB * CCH * CCH];      // reduced Gram per batch
__device__ float g_M[NB * CCH * CCH];      // effective 64x64 matrix per batch (fp32)
__device__ __nv_bfloat16 g_Mthi[NB * CCH * CCH]; // M^T hi, [b][c][cp]
__device__ __nv_bfloat16 g_Mtlo[NB * CCH * CCH]; // M^T lo

// ---------------- mma / ldmatrix helpers ----------------
__device__ __forceinline__ unsigned cvs(const void* p) {
    return (unsigned)__cvta_generic_to_shared(p);
}
__device__ __forceinline__ void ldm_x4(unsigned r[4], unsigned addr) {
    asm volatile("ldmatrix.sync.aligned.m8n8.x4.shared.b16 {%0,%1,%2,%3}, [%4];"
                 : "=r"(r[0]), "=r"(r[1]), "=r"(r[2]), "=r"(r[3]) : "r"(addr));
}
__device__ __forceinline__ void ldm_x2(unsigned r[2], unsigned addr) {
    asm volatile("ldmatrix.sync.aligned.m8n8.x2.shared.b16 {%0,%1}, [%2];"
                 : "=r"(r[0]), "=r"(r[1]) : "r"(addr));
}
__device__ __forceinline__ void ldm_x2t(unsigned r[2], unsigned addr) {
    asm volatile("ldmatrix.sync.aligned.m8n8.x2.trans.shared.b16 {%0,%1}, [%2];"
                 : "=r"(r[0]), "=r"(r[1]) : "r"(addr));
}
__device__ __forceinline__ void mma_bf16(float c[4], const unsigned a[4], const unsigned b[2]) {
    asm volatile(
        "mma.sync.aligned.m16n8k16.row.col.f32.bf16.bf16.f32 "
        "{%0,%1,%2,%3}, {%4,%5,%6,%7}, {%8,%9}, {%0,%1,%2,%3};"
        : "+f"(c[0]), "+f"(c[1]), "+f"(c[2]), "+f"(c[3])
        : "r"(a[0]), "r"(a[1]), "r"(a[2]), "r"(a[3]), "r"(b[0]), "r"(b[1]));
}
// split two floats into packed bf16x2 hi and lo (lo = x - float(hi), bf16-rounded)
__device__ __forceinline__ void split2(float a, float b, unsigned& hi2, unsigned& lo2) {
    unsigned h, l;
    asm("cvt.rn.bf16x2.f32 %0, %1, %2;" : "=r"(h) : "f"(b), "f"(a)); // low16=a, high16=b
    const float ha = __uint_as_float(h << 16);
    const float hb = __uint_as_float(h & 0xFFFF0000u);
    const float la = a - ha, lb = b - hb;
    asm("cvt.rn.bf16x2.f32 %0, %1, %2;" : "=r"(l) : "f"(lb), "f"(la));
    hi2 = h; lo2 = l;
}

// ---------------------------------------------------------------------------
// K1: partial Gram via bf16-split tensor MMA.
// grid = 256 (4 batches x 64 chunks of 256 tokens), 256 threads (8 warps).
// smem: xhi/xlo [64 ch][264] bf16 (token-contiguous rows).
// G tile (m=c1 16) x (n=c2 8): A = x[m][k] ldm x4; B = x[n][k] ldm x2 no-trans.
// ---------------------------------------------------------------------------
#define XS_STRIDE 264
#define K1_SBYTES (2 * 64 * XS_STRIDE * 2) // 67584

__global__ __launch_bounds__(256, 2) void gram_kernel(const float* __restrict__ x) {
    extern __shared__ unsigned short sm1[];
    unsigned short* xhi = sm1;
    unsigned short* xlo = sm1 + 64 * XS_STRIDE;

    const int b     = blockIdx.x >> 6;
    const int chunk = blockIdx.x & 63;
    const int n0    = chunk * 256;
    const int tid   = threadIdx.x;
    const int lane  = tid & 31;
    const int wid   = tid >> 5;
    const int l15   = lane & 15;

    const float* xb = x + (size_t)b * CCH * NTOK;

    // fill + convert: 4096 float4 / 256 thr = 16 each
#pragma unroll
    for (int r = 0; r < 16; ++r) {
        const int q  = r * 256 + tid;
        const int c  = q >> 6;
        const int t4 = q & 63;
        const float4 v = *reinterpret_cast<const float4*>(&xb[c * NTOK + n0 + 4 * t4]);
        unsigned h0, l0, h1, l1;
        split2(v.x, v.y, h0, l0);
        split2(v.z, v.w, h1, l1);
        *reinterpret_cast<uint2*>(&xhi[c * XS_STRIDE + 4 * t4]) = make_uint2(h0, h1);
        *reinterpret_cast<uint2*>(&xlo[c * XS_STRIDE + 4 * t4]) = make_uint2(l0, l1);
    }
    __syncthreads();

    // warp tiling: mt = wid&3 (c1 tile), nt = 4*(wid>>2)+j (c2 tiles)
    const int mt = wid & 3;
    const int ntb = 4 * (wid >> 2);

    float acc[4][4];
#pragma unroll
    for (int j = 0; j < 4; ++j)
#pragma unroll
        for (int k = 0; k < 4; ++k) acc[j][k] = 0.f;

    // A-frag lane address pieces (16x16 tile)
    const int aq   = lane >> 3;
    const int arow = 16 * mt + (aq & 1) * 8 + (lane & 7);
    const int acol_off = (aq >> 1) * 8;
    // B-frag lane address pieces (8x16 tile from [n][k] layout)
    const int brow_off = l15 & 7;
    const int bcol_off = (l15 >> 3) * 8;

#pragma unroll 4
    for (int kt = 0; kt < 16; ++kt) {
        const int K0 = 16 * kt;
        unsigned Ahi[4], Alo[4];
        ldm_x4(Ahi, cvs(&xhi[arow * XS_STRIDE + K0 + acol_off]));
        ldm_x4(Alo, cvs(&xlo[arow * XS_STRIDE + K0 + acol_off]));
#pragma unroll
        for (int j = 0; j < 4; ++j) {
            const int N0 = 8 * (ntb + j);
            unsigned Bhi[2], Blo[2];
            ldm_x2(Bhi, cvs(&xhi[(N0 + brow_off) * XS_STRIDE + K0 + bcol_off]));
            ldm_x2(Blo, cvs(&xlo[(N0 + brow_off) * XS_STRIDE + K0 + bcol_off]));
            mma_bf16(acc[j], Ahi, Bhi);
            mma_bf16(acc[j], Ahi, Blo);
            mma_bf16(acc[j], Alo, Bhi);
        }
    }

    // store partial G
    float* gp = g_Gpart + (size_t)blockIdx.x * 4096;
    const int g = lane >> 2, l = lane & 3;
#pragma unroll
    for (int j = 0; j < 4; ++j) {
        const int col0 = 8 * (ntb + j) + 2 * l;
        const int row0 = 16 * mt + g;
        *reinterpret_cast<float2*>(&gp[row0 * 64 + col0])       = make_float2(acc[j][0], acc[j][1]);
        *reinterpret_cast<float2*>(&gp[(row0 + 8) * 64 + col0]) = make_float2(acc[j][2], acc[j][3]);
    }
}

// ---------------------------------------------------------------------------
// K1b: reduce 64 partials per batch into g_G; also zero g_M.
// ---------------------------------------------------------------------------
__global__ __launch_bounds__(256) void reduce_gram_kernel() {
    const int i = blockIdx.x * 256 + threadIdx.x; // 0..16383
    const int b = i >> 12;
    const int idx = i & 4095;
    float s = 0.f;
    const float* gp = g_Gpart + (size_t)(b * 64) * 4096 + idx;
#pragma unroll 8
    for (int p = 0; p < 64; ++p) s += gp[(size_t)p * 4096];
    g_G[i] = s;
    g_M[i] = 0.f;
}

// ---------------------------------------------------------------------------
// K2: per (batch, head, d-half) attention math. (unchanged)
// ---------------------------------------------------------------------------
#define K2_SFLOATS 19072
#define K2_SBYTES  (K2_SFLOATS * 4)

__global__ __launch_bounds__(256) void attn_small_kernel(
    const float* __restrict__ Wq, const float* __restrict__ Wk,
    const float* __restrict__ Wv, const float* __restrict__ Wp,
    const float* __restrict__ rescale, float* __restrict__ attn_out) {
    extern __shared__ float smem[];
    float* sG  = smem;
    float* sA  = smem + 4160;
    float* sB  = smem + 8320;
    float* sT  = smem + 12480;
    float* sS  = smem + 16640;
    float* red = smem + 18720;
    float* snq = smem + 18976;
    float* snk = smem + 19040;

    const int bx   = blockIdx.x;
    const int b    = bx >> 4;
    const int h    = (bx >> 1) & 7;
    const int half = bx & 1;
    const int d0   = half * 32;
    const int tid  = threadIdx.x;
    const int ty   = tid >> 4;
    const int tx   = tid & 15;

    for (int r = 0; r < 16; ++r) {
        const int idx = r * 256 + tid;
        const int c = idx >> 6, c2 = idx & 63;
        sG[c * 65 + c2] = g_G[b * 4096 + idx];
        sA[c * 65 + c2] = Wq[c * INNER + h * 64 + c2];
        sB[c * 65 + c2] = Wk[c * INNER + h * 64 + c2];
    }
    __syncthreads();

    {
        float acc[4][4];
#pragma unroll
        for (int i = 0; i < 4; ++i)
#pragma unroll
            for (int j = 0; j < 4; ++j) acc[i][j] = 0.f;
#pragma unroll 4
        for (int cp = 0; cp < 64; ++cp) {
            float a[4], bb[4];
#pragma unroll
            for (int i = 0; i < 4; ++i) a[i]  = sG[(4 * ty + i) * 65 + cp];
#pragma unroll
            for (int j = 0; j < 4; ++j) bb[j] = sA[cp * 65 + 4 * tx + j];
#pragma unroll
            for (int i = 0; i < 4; ++i)
#pragma unroll
                for (int j = 0; j < 4; ++j) acc[i][j] = fmaf(a[i], bb[j], acc[i][j]);
        }
#pragma unroll
        for (int i = 0; i < 4; ++i)
#pragma unroll
            for (int j = 0; j < 4; ++j)
                sT[(4 * ty + i) * 65 + 4 * tx + j] = acc[i][j];
    }
    __syncthreads();

    {
        const int e = tid & 63, p = tid >> 6;
        float s = 0.f;
        for (int c = p * 16; c < p * 16 + 16; ++c) s += sA[c * 65 + e] * sT[c * 65 + e];
        red[p * 64 + e] = s;
    }
    __syncthreads();
    if (tid < 64) snq[tid] = sqrtf(red[tid] + red[64 + tid] + red[128 + tid] + red[192 + tid]);
    __syncthreads();

    {
        float acc[2][4] = {{0.f, 0.f, 0.f, 0.f}, {0.f, 0.f, 0.f, 0.f}};
#pragma unroll 4
        for (int cp = 0; cp < 64; ++cp) {
            float a[2], bb[4];
#pragma unroll
            for (int i = 0; i < 2; ++i) a[i]  = sB[cp * 65 + d0 + 2 * ty + i];
#pragma unroll
            for (int j = 0; j < 4; ++j) bb[j] = sG[cp * 65 + 4 * tx + j];
#pragma unroll
            for (int i = 0; i < 2; ++i)
#pragma unroll
                for (int j = 0; j < 4; ++j) acc[i][j] = fmaf(a[i], bb[j], acc[i][j]);
        }
#pragma unroll
        for (int i = 0; i < 2; ++i)
#pragma unroll
            for (int j = 0; j < 4; ++j)
                sS[(2 * ty + i) * 65 + 4 * tx + j] = acc[i][j];
    }
    __syncthreads();

    {
        const int d = tid & 31, p = tid >> 5;
        float s = 0.f;
        for (int c = p * 8; c < p * 8 + 8; ++c) s += sB[c * 65 + d0 + d] * sS[d * 65 + c];
        red[p * 32 + d] = s;
    }
    __syncthreads();
    if (tid < 32) {
        float s = 0.f;
#pragma unroll
        for (int p = 0; p < 8; ++p) s += red[p * 32 + tid];
        snk[tid] = sqrtf(s);
    }
    __syncthreads();

    {
        float acc[2][4] = {{0.f, 0.f, 0.f, 0.f}, {0.f, 0.f, 0.f, 0.f}};
#pragma unroll 4
        for (int cp = 0; cp < 64; ++cp) {
            float a[2], bb[4];
#pragma unroll
            for (int i = 0; i < 2; ++i) a[i]  = sB[cp * 65 + d0 + 2 * ty + i];
#pragma unroll
            for (int j = 0; j < 4; ++j) bb[j] = sT[cp * 65 + 4 * tx + j];
#pragma unroll
            for (int i = 0; i < 2; ++i)
#pragma unroll
                for (int j = 0; j < 4; ++j) acc[i][j] = fmaf(a[i], bb[j], acc[i][j]);
        }
        const float rs = rescale[h];
#pragma unroll
        for (int i = 0; i < 2; ++i)
#pragma unroll
            for (int j = 0; j < 4; ++j) {
                const int d = 2 * ty + i, e = 4 * tx + j;
                sS[d * 65 + e] = acc[i][j] * rs /
                                 (fmaxf(snk[d], EPSV) * fmaxf(snq[e], EPSV));
            }
    }
    __syncthreads();

    {
        const int w = tid >> 5, lane = tid & 31;
        for (int r = 0; r < 4; ++r) {
            const int d = w * 4 + r;
            float v0 = sS[d * 65 + lane];
            float v1 = sS[d * 65 + 32 + lane];
            float m = fmaxf(v0, v1);
#pragma unroll
            for (int o = 16; o > 0; o >>= 1) m = fmaxf(m, __shfl_xor_sync(0xffffffffu, m, o));
            float e0 = __expf(v0 - m), e1 = __expf(v1 - m);
            float s = e0 + e1;
#pragma unroll
            for (int o = 16; o > 0; o >>= 1) s += __shfl_xor_sync(0xffffffffu, s, o);
            const float inv = 1.f / s;
            e0 *= inv; e1 *= inv;
            sS[d * 65 + lane]      = e0;
            sS[d * 65 + 32 + lane] = e1;
            float* ao = attn_out + (((size_t)(b * NH + h) * DH) + d0 + d) * DH;
            ao[lane]      = e0;
            ao[32 + lane] = e1;
        }
    }
    __syncthreads();

    for (int r = 0; r < 16; ++r) {
        const int idx = r * 256 + tid;
        const int c = idx >> 6, e = idx & 63;
        sA[c * 65 + e] = Wv[c * INNER + h * 64 + e];
    }
    for (int r = 0; r < 8; ++r) {
        const int idx = r * 256 + tid;
        const int d = idx >> 6, c = idx & 63;
        sB[d * 65 + c] = Wp[(h * 64 + d0 + d) * CCH + c];
    }
    __syncthreads();

    {
        float acc[4][4];
#pragma unroll
        for (int i = 0; i < 4; ++i)
#pragma unroll
            for (int j = 0; j < 4; ++j) acc[i][j] = 0.f;
#pragma unroll 4
        for (int dk = 0; dk < 32; ++dk) {
            float a[4], bb[4];
#pragma unroll
            for (int i = 0; i < 4; ++i) a[i]  = sS[dk * 65 + 4 * ty + i];
#pragma unroll
            for (int j = 0; j < 4; ++j) bb[j] = sB[dk * 65 + 4 * tx + j];
#pragma unroll
            for (int i = 0; i < 4; ++i)
#pragma unroll
                for (int j = 0; j < 4; ++j) acc[i][j] = fmaf(a[i], bb[j], acc[i][j]);
        }
#pragma unroll
        for (int i = 0; i < 4; ++i)
#pragma unroll
            for (int j = 0; j < 4; ++j)
                sT[(4 * ty + i) * 65 + 4 * tx + j] = acc[i][j];
    }
    __syncthreads();

    {
        float acc[4][4];
#pragma unroll
        for (int i = 0; i < 4; ++i)
#pragma unroll
            for (int j = 0; j < 4; ++j) acc[i][j] = 0.f;
#pragma unroll 4
        for (int e = 0; e < 64; ++e) {
            float a[4], bb[4];
#pragma unroll
            for (int i = 0; i < 4; ++i) a[i]  = sA[(4 * ty + i) * 65 + e];
#pragma unroll
            for (int j = 0; j < 4; ++j) bb[j] = sT[e * 65 + 4 * tx + j];
#pragma unroll
            for (int i = 0; i < 4; ++i)
#pragma unroll
                for (int j = 0; j < 4; ++j) acc[i][j] = fmaf(a[i], bb[j], acc[i][j]);
        }
#pragma unroll
        for (int i = 0; i < 4; ++i)
#pragma unroll
            for (int j = 0; j < 4; ++j)
                atomicAdd(&g_M[b * 4096 + (4 * ty + i) * 64 + (4 * tx + j)], acc[i][j]);
    }
}

// ---------------------------------------------------------------------------
// K2b: g_M (fp32 [cp][c]) -> g_Mthi/lo (bf16, transposed [c][cp])
// ---------------------------------------------------------------------------
__global__ __launch_bounds__(256) void convert_M_kernel() {
    const int i = blockIdx.x * 256 + threadIdx.x; // 0..16383
    const int b = i >> 12;
    const int rem = i & 4095;
    const int cp = rem >> 6, c = rem & 63;
    const float v = g_M[i];
    const __nv_bfloat16 h = __float2bfloat16(v);
    const __nv_bfloat16 l = __float2bfloat16(v - __bfloat162float(h));
    g_Mthi[b * 4096 + c * 64 + cp] = h;
    g_Mtlo[b * 4096 + c * 64 + cp] = l;
}

// ---------------------------------------------------------------------------
// K3: out = M^T @ x via bf16-split tensor MMA.
// grid = 256 (4 batches x 64 segments of 256 tokens), 256 threads.
// A = Mt[c][cp] (ldm x4 no-trans); B = x[cp][tok] (ldm x2 TRANS).
// ---------------------------------------------------------------------------
#define MT_STRIDE 72
#define K3_SBYTES (2 * 64 * XS_STRIDE * 2 + 2 * 64 * MT_STRIDE * 2) // 67584+18432=86016

__global__ __launch_bounds__(256, 2) void out_kernel(const float* __restrict__ x,
                                                     const float* __restrict__ bp,
                                                     float* __restrict__ out) {
    extern __shared__ unsigned short sm3[];
    unsigned short* xhi = sm3;
    unsigned short* xlo = sm3 + 64 * XS_STRIDE;
    unsigned short* mhi = sm3 + 2 * 64 * XS_STRIDE;
    unsigned short* mlo = mhi + 64 * MT_STRIDE;

    const int b    = blockIdx.x >> 6;
    const int seg  = blockIdx.x & 63;
    const int n0   = seg * 256;
    const int tid  = threadIdx.x;
    const int lane = tid & 31;
    const int wid  = tid >> 5;
    const int l15  = lane & 15;

    const float* xb = x + (size_t)b * CCH * NTOK;
    float* ob = out + (size_t)b * CCH * NTOK;

    // fill x tile (convert to hi/lo)
#pragma unroll
    for (int r = 0; r < 16; ++r) {
        const int q  = r * 256 + tid;
        const int c  = q >> 6;
        const int t4 = q & 63;
        const float4 v = *reinterpret_cast<const float4*>(&xb[c * NTOK + n0 + 4 * t4]);
        unsigned h0, l0, h1, l1;
        split2(v.x, v.y, h0, l0);
        split2(v.z, v.w, h1, l1);
        *reinterpret_cast<uint2*>(&xhi[c * XS_STRIDE + 4 * t4]) = make_uint2(h0, h1);
        *reinterpret_cast<uint2*>(&xlo[c * XS_STRIDE + 4 * t4]) = make_uint2(l0, l1);
    }
    // fill Mt tiles (already bf16): 2048 u32 per plane / 256 thr = 8 each
    const unsigned* gmh = reinterpret_cast<const unsigned*>(&g_Mthi[b * 4096]);
    const unsigned* gml = reinterpret_cast<const unsigned*>(&g_Mtlo[b * 4096]);
#pragma unroll
    for (int r = 0; r < 8; ++r) {
        const int q = r * 256 + tid;      // 0..2047
        const int row = q >> 5, cp2 = q & 31;
        *reinterpret_cast<unsigned*>(&mhi[row * MT_STRIDE + 2 * cp2]) = gmh[q];
        *reinterpret_cast<unsigned*>(&mlo[row * MT_STRIDE + 2 * cp2]) = gml[q];
    }
    __syncthreads();

    // warp tiling: mt = wid&3 (c tile), nt = 16*(wid>>2)+j (token tiles, j 0..15)
    const int mt  = wid & 3;
    const int ntb = 16 * (wid >> 2);

    float acc[16][4];
#pragma unroll
    for (int j = 0; j < 16; ++j)
#pragma unroll
        for (int k = 0; k < 4; ++k) acc[j][k] = 0.f;

    const int aq   = lane >> 3;
    const int arow = 16 * mt + (aq & 1) * 8 + (lane & 7);
    const int acol_off = (aq >> 1) * 8;

#pragma unroll
    for (int kt = 0; kt < 4; ++kt) {
        const int K0 = 16 * kt;
        unsigned Ahi[4], Alo[4];
        ldm_x4(Ahi, cvs(&mhi[arow * MT_STRIDE + K0 + acol_off]));
        ldm_x4(Alo, cvs(&mlo[arow * MT_STRIDE + K0 + acol_off]));
        const int brow = K0 + l15; // k rows 0..15
#pragma unroll
        for (int j = 0; j < 16; ++j) {
            const int T0 = 8 * (ntb + j);
            unsigned Bhi[2], Blo[2];
            ldm_x2t(Bhi, cvs(&xhi[brow * XS_STRIDE + T0]));
            ldm_x2t(Blo, cvs(&xlo[brow * XS_STRIDE + T0]));
            mma_bf16(acc[j], Ahi, Bhi);
            mma_bf16(acc[j], Ahi, Blo);
            mma_bf16(acc[j], Alo, Bhi);
        }
    }

    // epilogue: add bias, store
    const int g = lane >> 2, l = lane & 3;
    const int r0 = 16 * mt + g;
    const float bp0 = bp[r0], bp1 = bp[r0 + 8];
#pragma unroll
    for (int j = 0; j < 16; ++j) {
        const int tok = n0 + 8 * (ntb + j) + 2 * l;
        *reinterpret_cast<float2*>(&ob[r0 * NTOK + tok]) =
            make_float2(acc[j][0] + bp0, acc[j][1] + bp0);
        *reinterpret_cast<float2*>(&ob[(r0 + 8) * NTOK + tok]) =
            make_float2(acc[j][2] + bp1, acc[j][3] + bp1);
    }
}

// ---------------------------------------------------------------------------
extern "C" void kernel_launch(void* const* d_in, const int* in_sizes, int n_in,
                              void* d_out, int out_size) {
    const float* x       = (const float*)d_in[0];
    const float* Wq      = (const float*)d_in[1];
    const float* Wk      = (const float*)d_in[2];
    const float* Wv      = (const float*)d_in[3];
    const float* Wp      = (const float*)d_in[4];
    const float* bp      = (const float*)d_in[5];
    const float* rescale = (const float*)d_in[6];
    float* out      = (float*)d_out;
    float* attn_out = out + OUT_ELEMS;

    cudaFuncSetAttribute(gram_kernel,
                         cudaFuncAttributeMaxDynamicSharedMemorySize, K1_SBYTES);
    cudaFuncSetAttribute(attn_small_kernel,
                         cudaFuncAttributeMaxDynamicSharedMemorySize, K2_SBYTES);
    cudaFuncSetAttribute(out_kernel,
                         cudaFuncAttributeMaxDynamicSharedMemorySize, K3_SBYTES);

    gram_kernel<<<256, 256, K1_SBYTES>>>(x);
    reduce_gram_kernel<<<64, 256>>>();
    attn_small_kernel<<<64, 256, K2_SBYTES>>>(Wq, Wk, Wv, Wp, rescale, attn_out);
    convert_M_kernel<<<64, 256>>>();
    out_kernel<<<256, 256, K3_SBYTES>>>(x, bp, out);
}

// round 7
// speedup vs baseline: 2.1045x; 1.1157x over previous
#include <cuda_runtime.h>
#include <cuda_bf16.h>
#include <math.h>

#define NB    4
#define CCH   64
#define NTOK  16384
#define NH    8
#define DH    64
#define INNER 512
#define EPSV  1e-12f

#define OUT_ELEMS  (NB * CCH * NTOK)   // 4194304
#define ATTN_ELEMS (NB * NH * DH * DH) // 131072

// Scratch (static device globals; no allocation allowed)
__device__ float g_Gpart[256 * CCH * CCH]; // per-block partial Gram matrices
__device__ float g_G[NB * CCH * CCH];      // reduced Gram per batch
__device__ float g_M[NB * CCH * CCH];      // effective 64x64 matrix per batch (fp32)

// ---------------- mma / ldmatrix helpers ----------------
__device__ __forceinline__ unsigned cvs(const void* p) {
    return (unsigned)__cvta_generic_to_shared(p);
}
__device__ __forceinline__ void ldm_x4(unsigned r[4], unsigned addr) {
    asm volatile("ldmatrix.sync.aligned.m8n8.x4.shared.b16 {%0,%1,%2,%3}, [%4];"
                 : "=r"(r[0]), "=r"(r[1]), "=r"(r[2]), "=r"(r[3]) : "r"(addr));
}
__device__ __forceinline__ void ldm_x2(unsigned r[2], unsigned addr) {
    asm volatile("ldmatrix.sync.aligned.m8n8.x2.shared.b16 {%0,%1}, [%2];"
                 : "=r"(r[0]), "=r"(r[1]) : "r"(addr));
}
__device__ __forceinline__ void ldm_x2t(unsigned r[2], unsigned addr) {
    asm volatile("ldmatrix.sync.aligned.m8n8.x2.trans.shared.b16 {%0,%1}, [%2];"
                 : "=r"(r[0]), "=r"(r[1]) : "r"(addr));
}
__device__ __forceinline__ void mma_bf16(float c[4], const unsigned a[4], const unsigned b[2]) {
    asm volatile(
        "mma.sync.aligned.m16n8k16.row.col.f32.bf16.bf16.f32 "
        "{%0,%1,%2,%3}, {%4,%5,%6,%7}, {%8,%9}, {%0,%1,%2,%3};"
        : "+f"(c[0]), "+f"(c[1]), "+f"(c[2]), "+f"(c[3])
        : "r"(a[0]), "r"(a[1]), "r"(a[2]), "r"(a[3]), "r"(b[0]), "r"(b[1]));
}
// split two floats into packed bf16x2 hi and lo
__device__ __forceinline__ void split2(float a, float b, unsigned& hi2, unsigned& lo2) {
    unsigned h, l;
    asm("cvt.rn.bf16x2.f32 %0, %1, %2;" : "=r"(h) : "f"(b), "f"(a));
    const float ha = __uint_as_float(h << 16);
    const float hb = __uint_as_float(h & 0xFFFF0000u);
    const float la = a - ha, lb = b - hb;
    asm("cvt.rn.bf16x2.f32 %0, %1, %2;" : "=r"(l) : "f"(lb), "f"(la));
    hi2 = h; lo2 = l;
}

// ---------------------------------------------------------------------------
// K1: partial Gram via bf16-split tensor MMA. (unchanged from R6)
// ---------------------------------------------------------------------------
#define XS_STRIDE 264
#define K1_SBYTES (2 * 64 * XS_STRIDE * 2) // 67584

__global__ __launch_bounds__(256, 2) void gram_kernel(const float* __restrict__ x) {
    extern __shared__ unsigned short sm1[];
    unsigned short* xhi = sm1;
    unsigned short* xlo = sm1 + 64 * XS_STRIDE;

    const int b     = blockIdx.x >> 6;
    const int chunk = blockIdx.x & 63;
    const int n0    = chunk * 256;
    const int tid   = threadIdx.x;
    const int lane  = tid & 31;
    const int wid   = tid >> 5;
    const int l15   = lane & 15;

    const float* xb = x + (size_t)b * CCH * NTOK;

#pragma unroll
    for (int r = 0; r < 16; ++r) {
        const int q  = r * 256 + tid;
        const int c  = q >> 6;
        const int t4 = q & 63;
        const float4 v = *reinterpret_cast<const float4*>(&xb[c * NTOK + n0 + 4 * t4]);
        unsigned h0, l0, h1, l1;
        split2(v.x, v.y, h0, l0);
        split2(v.z, v.w, h1, l1);
        *reinterpret_cast<uint2*>(&xhi[c * XS_STRIDE + 4 * t4]) = make_uint2(h0, h1);
        *reinterpret_cast<uint2*>(&xlo[c * XS_STRIDE + 4 * t4]) = make_uint2(l0, l1);
    }
    __syncthreads();

    const int mt = wid & 3;
    const int ntb = 4 * (wid >> 2);

    float acc[4][4];
#pragma unroll
    for (int j = 0; j < 4; ++j)
#pragma unroll
        for (int k = 0; k < 4; ++k) acc[j][k] = 0.f;

    const int aq   = lane >> 3;
    const int arow = 16 * mt + (aq & 1) * 8 + (lane & 7);
    const int acol_off = (aq >> 1) * 8;
    const int brow_off = l15 & 7;
    const int bcol_off = (l15 >> 3) * 8;

#pragma unroll 4
    for (int kt = 0; kt < 16; ++kt) {
        const int K0 = 16 * kt;
        unsigned Ahi[4], Alo[4];
        ldm_x4(Ahi, cvs(&xhi[arow * XS_STRIDE + K0 + acol_off]));
        ldm_x4(Alo, cvs(&xlo[arow * XS_STRIDE + K0 + acol_off]));
#pragma unroll
        for (int j = 0; j < 4; ++j) {
            const int N0 = 8 * (ntb + j);
            unsigned Bhi[2], Blo[2];
            ldm_x2(Bhi, cvs(&xhi[(N0 + brow_off) * XS_STRIDE + K0 + bcol_off]));
            ldm_x2(Blo, cvs(&xlo[(N0 + brow_off) * XS_STRIDE + K0 + bcol_off]));
            mma_bf16(acc[j], Ahi, Bhi);
            mma_bf16(acc[j], Ahi, Blo);
            mma_bf16(acc[j], Alo, Bhi);
        }
    }

    float* gp = g_Gpart + (size_t)blockIdx.x * 4096;
    const int g = lane >> 2, l = lane & 3;
#pragma unroll
    for (int j = 0; j < 4; ++j) {
        const int col0 = 8 * (ntb + j) + 2 * l;
        const int row0 = 16 * mt + g;
        *reinterpret_cast<float2*>(&gp[row0 * 64 + col0])       = make_float2(acc[j][0], acc[j][1]);
        *reinterpret_cast<float2*>(&gp[(row0 + 8) * 64 + col0]) = make_float2(acc[j][2], acc[j][3]);
    }
}

// ---------------------------------------------------------------------------
// K1b: reduce 64 partials per batch into g_G; also zero g_M.
// ---------------------------------------------------------------------------
__global__ __launch_bounds__(256) void reduce_gram_kernel() {
    const int i = blockIdx.x * 256 + threadIdx.x;
    const int b = i >> 12;
    const int idx = i & 4095;
    float s = 0.f;
    const float* gp = g_Gpart + (size_t)(b * 64) * 4096 + idx;
#pragma unroll 8
    for (int p = 0; p < 64; ++p) s += gp[(size_t)p * 4096];
    g_G[i] = s;
    g_M[i] = 0.f;
}

// ---------------------------------------------------------------------------
// K2: per (batch, head, d-half) attention math. Vectorized float4/float2
// operands everywhere (G symmetry gives [k][m] access for A-operands;
// Wv loaded transposed for the final M-stage).
// ---------------------------------------------------------------------------
#define S2 68
#define K2_SFLOATS (4 * 64 * S2 + 32 * S2 + 256 + 64 + 32)
#define K2_SBYTES  (K2_SFLOATS * 4)

__global__ __launch_bounds__(256) void attn_small_kernel(
    const float* __restrict__ Wq, const float* __restrict__ Wk,
    const float* __restrict__ Wv, const float* __restrict__ Wp,
    const float* __restrict__ rescale, float* __restrict__ attn_out) {
    extern __shared__ float smem[];
    float* sG  = smem;                 // 64xS2 : Gram (symmetric)
    float* sA  = smem + 64 * S2;       // 64xS2 : Wq_h, later Wv_h^T [e][c]
    float* sB  = smem + 2 * 64 * S2;   // 64xS2 : Wk_h, later Wp_h (32 rows)
    float* sT  = smem + 3 * 64 * S2;   // 64xS2 : T1 = G@Wq_h, later P [e][c]
    float* sS  = smem + 4 * 64 * S2;   // 32xS2 : T2t, later attn logits/probs
    float* red = sS + 32 * S2;         // 256
    float* snq = red + 256;            // 64
    float* snk = snq + 64;             // 32

    const int bx   = blockIdx.x;
    const int b    = bx >> 4;
    const int h    = (bx >> 1) & 7;
    const int half = bx & 1;
    const int d0   = half * 32;
    const int tid  = threadIdx.x;
    const int ty   = tid >> 4;
    const int tx   = tid & 15;

    // fill G, Wq_h, Wk_h (float4 both sides; 1024 f4 each / 256 thr = 4)
#pragma unroll
    for (int r = 0; r < 4; ++r) {
        const int q    = r * 256 + tid;
        const int row  = q >> 4;
        const int col4 = (q & 15) * 4;
        *reinterpret_cast<float4*>(&sG[row * S2 + col4]) =
            *reinterpret_cast<const float4*>(&g_G[b * 4096 + row * 64 + col4]);
        *reinterpret_cast<float4*>(&sA[row * S2 + col4]) =
            *reinterpret_cast<const float4*>(&Wq[row * INNER + h * 64 + col4]);
        *reinterpret_cast<float4*>(&sB[row * S2 + col4]) =
            *reinterpret_cast<const float4*>(&Wk[row * INNER + h * 64 + col4]);
    }
    __syncthreads();

    // T1 = G @ Wq_h (A via G symmetry: a4 = G[k][4ty..])
    {
        float acc[4][4];
#pragma unroll
        for (int i = 0; i < 4; ++i)
#pragma unroll
            for (int j = 0; j < 4; ++j) acc[i][j] = 0.f;
#pragma unroll 4
        for (int cp = 0; cp < 64; ++cp) {
            const float4 a4 = *reinterpret_cast<const float4*>(&sG[cp * S2 + 4 * ty]);
            const float4 b4 = *reinterpret_cast<const float4*>(&sA[cp * S2 + 4 * tx]);
            const float a[4] = {a4.x, a4.y, a4.z, a4.w};
            const float bb[4] = {b4.x, b4.y, b4.z, b4.w};
#pragma unroll
            for (int i = 0; i < 4; ++i)
#pragma unroll
                for (int j = 0; j < 4; ++j) acc[i][j] = fmaf(a[i], bb[j], acc[i][j]);
        }
#pragma unroll
        for (int i = 0; i < 4; ++i)
            *reinterpret_cast<float4*>(&sT[(4 * ty + i) * S2 + 4 * tx]) =
                make_float4(acc[i][0], acc[i][1], acc[i][2], acc[i][3]);
    }
    __syncthreads();

    // nq[e] = sqrt(sum_c Wq[c,e] * T1[c,e])
    {
        const int e = tid & 63, p = tid >> 6;
        float s = 0.f;
        for (int c = p * 16; c < p * 16 + 16; ++c) s += sA[c * S2 + e] * sT[c * S2 + e];
        red[p * 64 + e] = s;
    }
    __syncthreads();
    if (tid < 64) snq[tid] = sqrtf(red[tid] + red[64 + tid] + red[128 + tid] + red[192 + tid]);
    __syncthreads();

    // T2t[d][c] = sum_cp Wk[cp][d0+d] * G[cp][c]  (32x64 into sS)
    {
        float acc[2][4] = {{0.f,0.f,0.f,0.f},{0.f,0.f,0.f,0.f}};
#pragma unroll 4
        for (int cp = 0; cp < 64; ++cp) {
            const float2 a2 = *reinterpret_cast<const float2*>(&sB[cp * S2 + d0 + 2 * ty]);
            const float4 b4 = *reinterpret_cast<const float4*>(&sG[cp * S2 + 4 * tx]);
            const float a[2] = {a2.x, a2.y};
            const float bb[4] = {b4.x, b4.y, b4.z, b4.w};
#pragma unroll
            for (int i = 0; i < 2; ++i)
#pragma unroll
                for (int j = 0; j < 4; ++j) acc[i][j] = fmaf(a[i], bb[j], acc[i][j]);
        }
#pragma unroll
        for (int i = 0; i < 2; ++i)
            *reinterpret_cast<float4*>(&sS[(2 * ty + i) * S2 + 4 * tx]) =
                make_float4(acc[i][0], acc[i][1], acc[i][2], acc[i][3]);
    }
    __syncthreads();

    // nk[d]
    {
        const int d = tid & 31, p = tid >> 5;
        float s = 0.f;
        for (int c = p * 8; c < p * 8 + 8; ++c) s += sB[c * S2 + d0 + d] * sS[d * S2 + c];
        red[p * 32 + d] = s;
    }
    __syncthreads();
    if (tid < 32) {
        float s = 0.f;
#pragma unroll
        for (int p = 0; p < 8; ++p) s += red[p * 32 + tid];
        snk[tid] = sqrtf(s);
    }
    __syncthreads();

    // logits[d][e]
    {
        float acc[2][4] = {{0.f,0.f,0.f,0.f},{0.f,0.f,0.f,0.f}};
#pragma unroll 4
        for (int cp = 0; cp < 64; ++cp) {
            const float2 a2 = *reinterpret_cast<const float2*>(&sB[cp * S2 + d0 + 2 * ty]);
            const float4 b4 = *reinterpret_cast<const float4*>(&sT[cp * S2 + 4 * tx]);
            const float a[2] = {a2.x, a2.y};
            const float bb[4] = {b4.x, b4.y, b4.z, b4.w};
#pragma unroll
            for (int i = 0; i < 2; ++i)
#pragma unroll
                for (int j = 0; j < 4; ++j) acc[i][j] = fmaf(a[i], bb[j], acc[i][j]);
        }
        const float rs = rescale[h];
        __syncthreads(); // sS (T2t) consumed; safe to overwrite
#pragma unroll
        for (int i = 0; i < 2; ++i)
#pragma unroll
            for (int j = 0; j < 4; ++j) {
                const int d = 2 * ty + i, e = 4 * tx + j;
                sS[d * S2 + e] = acc[i][j] * rs /
                                 (fmaxf(snk[d], EPSV) * fmaxf(snq[e], EPSV));
            }
    }
    __syncthreads();

    // softmax over e; write attn to output
    {
        const int w = tid >> 5, lane = tid & 31;
        for (int r = 0; r < 4; ++r) {
            const int d = w * 4 + r;
            float v0 = sS[d * S2 + lane];
            float v1 = sS[d * S2 + 32 + lane];
            float m = fmaxf(v0, v1);
#pragma unroll
            for (int o = 16; o > 0; o >>= 1) m = fmaxf(m, __shfl_xor_sync(0xffffffffu, m, o));
            float e0 = __expf(v0 - m), e1 = __expf(v1 - m);
            float s = e0 + e1;
#pragma unroll
            for (int o = 16; o > 0; o >>= 1) s += __shfl_xor_sync(0xffffffffu, s, o);
            const float inv = 1.f / s;
            e0 *= inv; e1 *= inv;
            sS[d * S2 + lane]      = e0;
            sS[d * S2 + 32 + lane] = e1;
            float* ao = attn_out + (((size_t)(b * NH + h) * DH) + d0 + d) * DH;
            ao[lane]      = e0;
            ao[32 + lane] = e1;
        }
    }
    __syncthreads();

    // reload: sA <- Wv_h^T [e][c], sB <- Wp_h rows [d0, d0+32)
    for (int r = 0; r < 16; ++r) {
        const int idx = r * 256 + tid;
        const int c = idx >> 6, e = idx & 63;
        sA[e * S2 + c] = Wv[c * INNER + h * 64 + e];
    }
#pragma unroll
    for (int r = 0; r < 2; ++r) {
        const int q    = r * 256 + tid;    // 0..511 -> 32 rows x 16 f4
        const int d    = q >> 4;
        const int col4 = (q & 15) * 4;
        *reinterpret_cast<float4*>(&sB[d * S2 + col4]) =
            *reinterpret_cast<const float4*>(&Wp[(h * 64 + d0 + d) * CCH + col4]);
    }
    __syncthreads();

    // P[e][c] = sum_d attn[d,e] * Wp[d0+d,c]  (into sT)
    {
        float acc[4][4];
#pragma unroll
        for (int i = 0; i < 4; ++i)
#pragma unroll
            for (int j = 0; j < 4; ++j) acc[i][j] = 0.f;
#pragma unroll 4
        for (int dk = 0; dk < 32; ++dk) {
            const float4 a4 = *reinterpret_cast<const float4*>(&sS[dk * S2 + 4 * ty]);
            const float4 b4 = *reinterpret_cast<const float4*>(&sB[dk * S2 + 4 * tx]);
            const float a[4] = {a4.x, a4.y, a4.z, a4.w};
            const float bb[4] = {b4.x, b4.y, b4.z, b4.w};
#pragma unroll
            for (int i = 0; i < 4; ++i)
#pragma unroll
                for (int j = 0; j < 4; ++j) acc[i][j] = fmaf(a[i], bb[j], acc[i][j]);
        }
#pragma unroll
        for (int i = 0; i < 4; ++i)
            *reinterpret_cast<float4*>(&sT[(4 * ty + i) * S2 + 4 * tx]) =
                make_float4(acc[i][0], acc[i][1], acc[i][2], acc[i][3]);
    }
    __syncthreads();

    // M[c1][c2] += sum_e WvT[e][c1] * P[e][c2]
    {
        float acc[4][4];
#pragma unroll
        for (int i = 0; i < 4; ++i)
#pragma unroll
            for (int j = 0; j < 4; ++j) acc[i][j] = 0.f;
#pragma unroll 4
        for (int e = 0; e < 64; ++e) {
            const float4 a4 = *reinterpret_cast<const float4*>(&sA[e * S2 + 4 * ty]);
            const float4 b4 = *reinterpret_cast<const float4*>(&sT[e * S2 + 4 * tx]);
            const float a[4] = {a4.x, a4.y, a4.z, a4.w};
            const float bb[4] = {b4.x, b4.y, b4.z, b4.w};
#pragma unroll
            for (int i = 0; i < 4; ++i)
#pragma unroll
                for (int j = 0; j < 4; ++j) acc[i][j] = fmaf(a[i], bb[j], acc[i][j]);
        }
#pragma unroll
        for (int i = 0; i < 4; ++i)
#pragma unroll
            for (int j = 0; j < 4; ++j)
                atomicAdd(&g_M[b * 4096 + (4 * ty + i) * 64 + (4 * tx + j)], acc[i][j]);
    }
}

// ---------------------------------------------------------------------------
// K3: out = M^T @ x via bf16-split tensor MMA. M converted+transposed+split
// in the prologue (no separate convert kernel).
// ---------------------------------------------------------------------------
#define MT_STRIDE 72
#define K3_SBYTES (2 * 64 * XS_STRIDE * 2 + 2 * 64 * MT_STRIDE * 2) // 86016

__global__ __launch_bounds__(256, 2) void out_kernel(const float* __restrict__ x,
                                                     const float* __restrict__ bp,
                                                     float* __restrict__ out) {
    extern __shared__ unsigned short sm3[];
    unsigned short* xhi = sm3;
    unsigned short* xlo = sm3 + 64 * XS_STRIDE;
    unsigned short* mhi = sm3 + 2 * 64 * XS_STRIDE;
    unsigned short* mlo = mhi + 64 * MT_STRIDE;

    const int b    = blockIdx.x >> 6;
    const int seg  = blockIdx.x & 63;
    const int n0   = seg * 256;
    const int tid  = threadIdx.x;
    const int lane = tid & 31;
    const int wid  = tid >> 5;
    const int l15  = lane & 15;

    const float* xb = x + (size_t)b * CCH * NTOK;
    float* ob = out + (size_t)b * CCH * NTOK;

    // fill x tile (convert to hi/lo)
#pragma unroll
    for (int r = 0; r < 16; ++r) {
        const int q  = r * 256 + tid;
        const int c  = q >> 6;
        const int t4 = q & 63;
        const float4 v = *reinterpret_cast<const float4*>(&xb[c * NTOK + n0 + 4 * t4]);
        unsigned h0, l0, h1, l1;
        split2(v.x, v.y, h0, l0);
        split2(v.z, v.w, h1, l1);
        *reinterpret_cast<uint2*>(&xhi[c * XS_STRIDE + 4 * t4]) = make_uint2(h0, h1);
        *reinterpret_cast<uint2*>(&xlo[c * XS_STRIDE + 4 * t4]) = make_uint2(l0, l1);
    }
    // fill Mt tiles: read fp32 g_M [cp][c], split + transpose -> [c][cp]
#pragma unroll
    for (int r = 0; r < 16; ++r) {
        const int q  = r * 256 + tid;   // 0..4095
        const int cp = q >> 6, c = q & 63;
        const float v = g_M[b * 4096 + q];
        const __nv_bfloat16 hh = __float2bfloat16(v);
        const __nv_bfloat16 ll = __float2bfloat16(v - __bfloat162float(hh));
        mhi[c * MT_STRIDE + cp] = __bfloat16_as_ushort(hh);
        mlo[c * MT_STRIDE + cp] = __bfloat16_as_ushort(ll);
    }
    __syncthreads();

    const int mt  = wid & 3;
    const int ntb = 16 * (wid >> 2);

    float acc[16][4];
#pragma unroll
    for (int j = 0; j < 16; ++j)
#pragma unroll
        for (int k = 0; k < 4; ++k) acc[j][k] = 0.f;

    const int aq   = lane >> 3;
    const int arow = 16 * mt + (aq & 1) * 8 + (lane & 7);
    const int acol_off = (aq >> 1) * 8;

#pragma unroll
    for (int kt = 0; kt < 4; ++kt) {
        const int K0 = 16 * kt;
        unsigned Ahi[4], Alo[4];
        ldm_x4(Ahi, cvs(&mhi[arow * MT_STRIDE + K0 + acol_off]));
        ldm_x4(Alo, cvs(&mlo[arow * MT_STRIDE + K0 + acol_off]));
        const int brow = K0 + l15;
#pragma unroll
        for (int j = 0; j < 16; ++j) {
            const int T0 = 8 * (ntb + j);
            unsigned Bhi[2], Blo[2];
            ldm_x2t(Bhi, cvs(&xhi[brow * XS_STRIDE + T0]));
            ldm_x2t(Blo, cvs(&xlo[brow * XS_STRIDE + T0]));
            mma_bf16(acc[j], Ahi, Bhi);
            mma_bf16(acc[j], Ahi, Blo);
            mma_bf16(acc[j], Alo, Bhi);
        }
    }

    const int g = lane >> 2, l = lane & 3;
    const int r0 = 16 * mt + g;
    const float bp0 = bp[r0], bp1 = bp[r0 + 8];
#pragma unroll
    for (int j = 0; j < 16; ++j) {
        const int tok = n0 + 8 * (ntb + j) + 2 * l;
        *reinterpret_cast<float2*>(&ob[r0 * NTOK + tok]) =
            make_float2(acc[j][0] + bp0, acc[j][1] + bp0);
        *reinterpret_cast<float2*>(&ob[(r0 + 8) * NTOK + tok]) =
            make_float2(acc[j][2] + bp1, acc[j][3] + bp1);
    }
}

// ---------------------------------------------------------------------------
extern "C" void kernel_launch(void* const* d_in, const int* in_sizes, int n_in,
                              void* d_out, int out_size) {
    const float* x       = (const float*)d_in[0];
    const float* Wq      = (const float*)d_in[1];
    const float* Wk      = (const float*)d_in[2];
    const float* Wv      = (const float*)d_in[3];
    const float* Wp      = (const float*)d_in[4];
    const float* bp      = (const float*)d_in[5];
    const float* rescale = (const float*)d_in[6];
    float* out      = (float*)d_out;
    float* attn_out = out + OUT_ELEMS;

    cudaFuncSetAttribute(gram_kernel,
                         cudaFuncAttributeMaxDynamicSharedMemorySize, K1_SBYTES);
    cudaFuncSetAttribute(attn_small_kernel,
                         cudaFuncAttributeMaxDynamicSharedMemorySize, K2_SBYTES);
    cudaFuncSetAttribute(out_kernel,
                         cudaFuncAttributeMaxDynamicSharedMemorySize, K3_SBYTES);

    gram_kernel<<<256, 256, K1_SBYTES>>>(x);
    reduce_gram_kernel<<<64, 256>>>();
    attn_small_kernel<<<64, 256, K2_SBYTES>>>(Wq, Wk, Wv, Wp, rescale, attn_out);
    out_kernel<<<256, 256, K3_SBYTES>>>(x, bp, out);
}